// round 9
// baseline (speedup 1.0000x reference)
#include <cuda_runtime.h>
#include <cuda_fp16.h>
#include <cstdint>
#include <cmath>

#define NB 32
#define FEAT 320
#define NPTS 2048

static __device__ float g_scratch[87162880];   // 348 MB

// byte offsets into scratch
#define O_SUPH 0LL
#define O_QRYH 41943040LL
#define O_WQH  83886080LL
#define O_WKH  92274688LL
#define O_WVH  100663296LL
#define O_QTH  109051904LL
#define O_KTH  150994944LL
#define O_VNH  192937984LL
#define O_ATF  234881024LL
#define O_PRH  247988224LL
#define O_TMPF 254541824LL

#define STAGE_BYTES 32768          // A 16KB + B 16KB (fp16, BK=64)
#define SMEM_TOTAL_BYTES (3 * STAGE_BYTES)

#define OM_HALF   0
#define OM_TRANS  1
#define OM_F32A   2
#define OM_F32RES 3

// ---------------- PTX helpers ----------------
__device__ __forceinline__ uint32_t smem_u32(const void* p) {
    uint32_t a;
    asm("{ .reg .u64 t; cvta.to.shared.u64 t, %1; cvt.u32.u64 %0, t; }" : "=r"(a) : "l"(p));
    return a;
}

__device__ __forceinline__ void mma_f16(float* d, const uint32_t* a, const uint32_t* b) {
    asm volatile(
        "mma.sync.aligned.m16n8k16.row.col.f32.f16.f16.f32 "
        "{%0,%1,%2,%3}, {%4,%5,%6,%7}, {%8,%9}, {%0,%1,%2,%3};"
        : "+f"(d[0]), "+f"(d[1]), "+f"(d[2]), "+f"(d[3])
        : "r"(a[0]), "r"(a[1]), "r"(a[2]), "r"(a[3]), "r"(b[0]), "r"(b[1]));
}

__device__ __forceinline__ void ldsm4(uint32_t* r, uint32_t addr) {
    asm volatile("ldmatrix.sync.aligned.m8n8.x4.shared.b16 {%0,%1,%2,%3}, [%4];"
                 : "=r"(r[0]), "=r"(r[1]), "=r"(r[2]), "=r"(r[3]) : "r"(addr));
}

__device__ __forceinline__ void cpasync16(uint32_t dst, const void* src, bool pred) {
    int sz = pred ? 16 : 0;
    asm volatile("cp.async.cg.shared.global [%0], [%1], 16, %2;"
                 :: "r"(dst), "l"(src), "r"(sz) : "memory");
}
#define CP_COMMIT() asm volatile("cp.async.commit_group;" ::: "memory")
#define CP_WAIT1()  asm volatile("cp.async.wait_group 1;" ::: "memory")

// ---------------- fp16 tile core (register-pipelined) — unchanged from R8 ----------------
template<int OM>
__device__ __forceinline__ void run_tile_h(
    const __half* __restrict__ A, const __half* __restrict__ B,
    char* __restrict__ Cb, const float* __restrict__ D,
    int M, int N, int K, int lda, int ldb, int ldc, long long sCb,
    int bm, int bn, float alpha, uint32_t sb, char* smem)
{
    const int tid  = threadIdx.x;
    const int lane = tid & 31;
    const int warp = tid >> 5;
    const int wm = warp & 1;
    const int wn = warp >> 1;

    const int r0  = tid >> 3;          // 0..15
    const int seg = tid & 7;
    const uint32_t xorterm = (uint32_t)((seg ^ (r0 & 7)) << 4);

    // ldmatrix lane->address decomposition
    const int mrowA = ((lane >> 3) & 1) * 8 + (lane & 7);
    const int khA   = lane >> 4;              // 0/1
    const int nrowB = (lane >> 4) * 8 + (lane & 7);
    const int khB   = (lane >> 3) & 1;
    uint32_t offA[4], phA[4], offB[4], phB[4];
#pragma unroll
    for (int mt = 0; mt < 4; mt++) {
        int rowA = wm * 64 + mt * 16 + mrowA;
        offA[mt] = (uint32_t)(rowA * 128);
        phA[mt]  = (uint32_t)(rowA & 7);
    }
#pragma unroll
    for (int np = 0; np < 4; np++) {
        int rowB = wn * 64 + np * 16 + nrowB;
        offB[np] = (uint32_t)(rowB * 128);
        phB[np]  = (uint32_t)(rowB & 7);
    }

    float acc[4][8][4];
#pragma unroll
    for (int i = 0; i < 4; i++)
#pragma unroll
        for (int j = 0; j < 8; j++)
#pragma unroll
            for (int r = 0; r < 4; r++) acc[i][j][r] = 0.f;

    const int NC = K >> 6;   // BK=64

    auto ISSUE = [&](int c) {
        const int k0 = c << 6;
        const uint32_t aB = sb + (uint32_t)((c % 3) * STAGE_BYTES);
        const uint32_t bB = aB + 16384;
#pragma unroll
        for (int i = 0; i < 8; i++) {
            int r = r0 + 16 * i;
            int gr = bm + r;
            bool p = gr < M;
            cpasync16(aB + (uint32_t)(r * 128) + xorterm,
                      A + (long long)(p ? gr : 0) * lda + k0 + seg * 8, p);
        }
#pragma unroll
        for (int i = 0; i < 8; i++) {
            int r = r0 + 16 * i;
            int gn = bn + r;
            bool p = gn < N;
            cpasync16(bB + (uint32_t)(r * 128) + xorterm,
                      B + (long long)(p ? gn : 0) * ldb + k0 + seg * 8, p);
        }
        CP_COMMIT();
    };

    // 2-stage register fragment pipeline
    uint32_t afr[2][4][4];
    uint32_t bfr[2][8][2];

    ISSUE(0);
    ISSUE(1);

    for (int c = 0; c < NC; c++) {
        CP_WAIT1();
        __syncthreads();

        const uint32_t aB = sb + (uint32_t)((c % 3) * STAGE_BYTES);
        const uint32_t bB = aB + 16384;

        // preload ks=0 fragments into buffer 0 (latency covered by ISSUE below)
        {
            const uint32_t s16 = (uint32_t)khA;
#pragma unroll
            for (int mt = 0; mt < 4; mt++)
                ldsm4(afr[0][mt], aB + offA[mt] + ((s16 ^ phA[mt]) << 4));
        }
        {
            const uint32_t s16 = (uint32_t)khB;
#pragma unroll
            for (int np = 0; np < 4; np++) {
                uint32_t r[4];
                ldsm4(r, bB + offB[np] + ((s16 ^ phB[np]) << 4));
                bfr[0][2 * np][0] = r[0];     bfr[0][2 * np][1] = r[1];
                bfr[0][2 * np + 1][0] = r[2]; bfr[0][2 * np + 1][1] = r[3];
            }
        }

        if (c + 2 < NC) ISSUE(c + 2);
        else CP_COMMIT();

#pragma unroll
        for (int ks = 0; ks < 4; ks++) {
            const int cur = ks & 1;
            const int nxt = cur ^ 1;
            if (ks < 3) {
                const uint32_t sA16 = (uint32_t)(2 * (ks + 1) + khA);
#pragma unroll
                for (int mt = 0; mt < 4; mt++)
                    ldsm4(afr[nxt][mt], aB + offA[mt] + ((sA16 ^ phA[mt]) << 4));
                const uint32_t sB16 = (uint32_t)(2 * (ks + 1) + khB);
#pragma unroll
                for (int np = 0; np < 4; np++) {
                    uint32_t r[4];
                    ldsm4(r, bB + offB[np] + ((sB16 ^ phB[np]) << 4));
                    bfr[nxt][2 * np][0] = r[0];     bfr[nxt][2 * np][1] = r[1];
                    bfr[nxt][2 * np + 1][0] = r[2]; bfr[nxt][2 * np + 1][1] = r[3];
                }
            }
#pragma unroll
            for (int mt = 0; mt < 4; mt++)
#pragma unroll
                for (int nt = 0; nt < 8; nt++)
                    mma_f16(acc[mt][nt], afr[cur][mt], bfr[cur][nt]);
        }
    }

    // ---------------- epilogues ----------------
    if (OM == OM_HALF) {
        __half* C = (__half*)Cb;
#pragma unroll
        for (int mt = 0; mt < 4; mt++) {
#pragma unroll
            for (int nt = 0; nt < 8; nt++) {
                int row = bm + wm * 64 + mt * 16 + (lane >> 2);
                int col = bn + wn * 64 + nt * 8 + ((lane & 3) << 1);
                __half2 h0 = __float22half2_rn(make_float2(acc[mt][nt][0], acc[mt][nt][1]));
                __half2 h1 = __float22half2_rn(make_float2(acc[mt][nt][2], acc[mt][nt][3]));
                *reinterpret_cast<__half2*>(C + (long long)row * ldc + col) = h0;
                *reinterpret_cast<__half2*>(C + (long long)(row + 8) * ldc + col) = h1;
            }
        }
    } else if (OM == OM_F32A || OM == OM_F32RES) {
        float* C = (float*)Cb;
#pragma unroll
        for (int mt = 0; mt < 4; mt++) {
#pragma unroll
            for (int nt = 0; nt < 8; nt++) {
                int row = bm + wm * 64 + mt * 16 + (lane >> 2);
                int col = bn + wn * 64 + nt * 8 + ((lane & 3) << 1);
                if (col < N) {
                    if (row < M) {
                        long long i0 = (long long)row * ldc + col;
                        float2 v;
                        v.x = alpha * acc[mt][nt][0];
                        v.y = alpha * acc[mt][nt][1];
                        if (OM == OM_F32RES) { v.x += D[i0]; v.y += D[i0 + 1]; }
                        *reinterpret_cast<float2*>(C + i0) = v;
                    }
                    if (row + 8 < M) {
                        long long i1 = (long long)(row + 8) * ldc + col;
                        float2 v;
                        v.x = alpha * acc[mt][nt][2];
                        v.y = alpha * acc[mt][nt][3];
                        if (OM == OM_F32RES) { v.x += D[i1]; v.y += D[i1 + 1]; }
                        *reinterpret_cast<float2*>(C + i1) = v;
                    }
                }
            }
        }
    } else {   // OM_TRANS: scatter C[b][n][m%FEAT] as fp16 via smem staging
        float* Cs = reinterpret_cast<float*>(smem);
        __half* Ch = (__half*)Cb;
        __syncthreads();
#pragma unroll
        for (int mt = 0; mt < 4; mt++) {
#pragma unroll
            for (int nt = 0; nt < 8; nt++) {
                int nl = wn * 64 + nt * 8 + ((lane & 3) << 1);
                int m0 = wm * 64 + mt * 16 + (lane >> 2);
                Cs[nl * 132 + m0]           = acc[mt][nt][0];
                Cs[(nl + 1) * 132 + m0]     = acc[mt][nt][1];
                Cs[nl * 132 + m0 + 8]       = acc[mt][nt][2];
                Cs[(nl + 1) * 132 + m0 + 8] = acc[mt][nt][3];
            }
        }
        __syncthreads();
#pragma unroll
        for (int it = 0; it < 32; it++) {
            int linear = tid + it * 128;
            int row = linear >> 5;          // local n 0..127
            int c4  = linear & 31;          // 4-float group along m
            int n_g = bn + row;
            int m_g = bm + c4 * 4;          // flat m
            int bb  = m_g / FEAT;
            int mm  = m_g - bb * FEAT;
            float4 v = *reinterpret_cast<const float4*>(&Cs[row * 132 + c4 * 4]);
            __half2 h0 = __float22half2_rn(make_float2(v.x, v.y));
            __half2 h1 = __float22half2_rn(make_float2(v.z, v.w));
            __half2* dst = reinterpret_cast<__half2*>(
                Ch + (long long)bb * sCb + (long long)n_g * ldc + mm);
            dst[0] = h0; dst[1] = h1;
        }
    }
}

// ---------------- fused persistent QKV ----------------
#define QKV_TILES_PER_OP 1280
#define QKV_NTILES 3840

__global__ __launch_bounds__(128, 2)
void qkv_kernel(const __half* __restrict__ qryh, const __half* __restrict__ suph,
                const __half* __restrict__ wq, const __half* __restrict__ wk,
                const __half* __restrict__ wv,
                __half* __restrict__ qT, __half* __restrict__ kT, __half* __restrict__ vN)
{
    extern __shared__ char smem[];
    const uint32_t sb = smem_u32(smem);
    const long long sX = (long long)FEAT * NPTS;   // 655360 halfs per batch (vN)

    for (int t = blockIdx.x; t < QKV_NTILES; t += gridDim.x) {
        int op = t / QKV_TILES_PER_OP;
        int r  = t - op * QKV_TILES_PER_OP;
        int bm = (r >> 4) * 128;
        int bn = (r & 15) * 128;
        __syncthreads();
        if (op == 0) {
            run_tile_h<OM_HALF>(suph, wq, (char*)qT, nullptr,
                                NB * FEAT, 2048, 2048, 2048, 2048, 2048, 0,
                                bm, bn, 1.f, sb, smem);
        } else if (op == 1) {
            run_tile_h<OM_HALF>(qryh, wk, (char*)kT, nullptr,
                                NB * FEAT, 2048, 2048, 2048, 2048, 2048, 0,
                                bm, bn, 1.f, sb, smem);
        } else {
            run_tile_h<OM_TRANS>(qryh, wv, (char*)vN, nullptr,
                                 NB * FEAT, 2048, 2048, 2048, 2048, 320, sX,
                                 bm, bn, 1.f, sb, smem);
        }
    }
}

// ---------------- generic persistent batched GEMM (fp16 in) ----------------
template<int OM>
__global__ __launch_bounds__(128, 2)
void gemm_h_kernel(const __half* __restrict__ Ag, const __half* __restrict__ Bg,
                   char* __restrict__ Cg, const float* __restrict__ Dg,
                   int M, int N, int K, int lda, int ldb, int ldc,
                   long long sA, long long sB, long long sC, long long sD,
                   float alpha, int ntiles, int tn)
{
    extern __shared__ char smem[];
    const uint32_t sb = smem_u32(smem);
    const int per = ((M + 127) >> 7) * tn;
    const int esz = (OM == OM_HALF || OM == OM_TRANS) ? 2 : 4;

    for (int t = blockIdx.x; t < ntiles; t += gridDim.x) {
        int b = t / per;
        int r = t - b * per;
        int bm = (r / tn) * 128;
        int bn = (r % tn) * 128;
        __syncthreads();
        run_tile_h<OM>(Ag + (long long)b * sA, Bg + (long long)b * sB,
                       Cg + (long long)b * sC * esz,
                       Dg ? (Dg + (long long)b * sD) : nullptr,
                       M, N, K, lda, ldb, ldc, 0, bm, bn, alpha, sb, smem);
    }
}

// ---------------- fused high-MLP convert (all 5 tensors, 1 launch) ----------------
// flat index over float4 units: [0,5242880) support, [.. ,10485760) query,
// then Wq, Wk, Wv at 1048576 float4 each. 4 float4 per thread (MLP=4).
#define CVT_B0 5242880
#define CVT_B1 10485760
#define CVT_B2 11534336
#define CVT_B3 12582912
#define CVT_B4 13631488

__global__ __launch_bounds__(256) void cvt_all_kernel(
    const float* __restrict__ s,  const float* __restrict__ q,
    const float* __restrict__ w0, const float* __restrict__ w1, const float* __restrict__ w2,
    __half* __restrict__ sh, __half* __restrict__ qh,
    __half* __restrict__ h0, __half* __restrict__ h1, __half* __restrict__ h2)
{
    int t = blockIdx.x * 256 + threadIdx.x;
    long long base = (long long)t * 4;                 // float4 index, region-aligned
    const float* src; __half* dst; long long off;
    if (base < CVT_B0)      { src = s;  dst = sh; off = base; }
    else if (base < CVT_B1) { src = q;  dst = qh; off = base - CVT_B0; }
    else if (base < CVT_B2) { src = w0; dst = h0; off = base - CVT_B1; }
    else if (base < CVT_B3) { src = w1; dst = h1; off = base - CVT_B2; }
    else if (base < CVT_B4) { src = w2; dst = h2; off = base - CVT_B3; }
    else return;
    float4 v[4];
#pragma unroll
    for (int i = 0; i < 4; i++)
        v[i] = reinterpret_cast<const float4*>(src)[off + i];
#pragma unroll
    for (int i = 0; i < 4; i++) {
        __half2 a = __float22half2_rn(make_float2(v[i].x, v[i].y));
        __half2 b = __float22half2_rn(make_float2(v[i].z, v[i].w));
        uint2 u;
        u.x = *reinterpret_cast<uint32_t*>(&a);
        u.y = *reinterpret_cast<uint32_t*>(&b);
        reinterpret_cast<uint2*>(dst)[off + i] = u;
    }
}

// ---------------- softmax ----------------
__global__ __launch_bounds__(256) void softmax_kernel(const float* __restrict__ attn,
                                                      __half* __restrict__ probs)
{
    __shared__ float red[256];
    const int tid = threadIdx.x;
    const long long ro = ((long long)blockIdx.y * FEAT + blockIdx.x) * FEAT;
    const float* row = attn + ro;
    float v0 = row[tid];
    float v1 = (tid < FEAT - 256) ? row[tid + 256] : -1e30f;
    red[tid] = fmaxf(v0, v1);
    __syncthreads();
#pragma unroll
    for (int s = 128; s > 0; s >>= 1) {
        if (tid < s) red[tid] = fmaxf(red[tid], red[tid + s]);
        __syncthreads();
    }
    float m = red[0];
    __syncthreads();
    float e0 = expf(v0 - m);
    float e1 = (tid < FEAT - 256) ? expf(v1 - m) : 0.f;
    red[tid] = e0 + e1;
    __syncthreads();
#pragma unroll
    for (int s = 128; s > 0; s >>= 1) {
        if (tid < s) red[tid] += red[tid + s];
        __syncthreads();
    }
    float inv = 1.f / red[0];
    __half* orow = probs + ro;
    orow[tid] = __float2half(e0 * inv);
    if (tid < FEAT - 256) orow[tid + 256] = __float2half(e1 * inv);
}

// ---------------- vectorized LayerNorm (float4 columns, MLP-8) ----------------
__global__ __launch_bounds__(256) void ln_kernel(const float* __restrict__ tp,
                                                 const float* __restrict__ gamma,
                                                 const float* __restrict__ beta,
                                                 float* __restrict__ out)
{
    const int b  = blockIdx.y;
    const int o4 = blockIdx.x * 256 + threadIdx.x;      // float4 column group (NPTS/4=512)
    const float4* base = reinterpret_cast<const float4*>(tp + (long long)b * (FEAT * NPTS)) + o4;

    float4 s  = make_float4(0.f, 0.f, 0.f, 0.f);
    float4 s2 = make_float4(0.f, 0.f, 0.f, 0.f);
#pragma unroll 8
    for (int l = 0; l < FEAT; l++) {
        float4 v = base[l * (NPTS / 4)];
        s.x += v.x;  s.y += v.y;  s.z += v.z;  s.w += v.w;
        s2.x += v.x * v.x;  s2.y += v.y * v.y;  s2.z += v.z * v.z;  s2.w += v.w * v.w;
    }
    const float inv = 1.f / FEAT;
    float4 mu = make_float4(s.x * inv, s.y * inv, s.z * inv, s.w * inv);
    float4 rs;
    rs.x = rsqrtf(s2.x * inv - mu.x * mu.x + 1e-5f);
    rs.y = rsqrtf(s2.y * inv - mu.y * mu.y + 1e-5f);
    rs.z = rsqrtf(s2.z * inv - mu.z * mu.z + 1e-5f);
    rs.w = rsqrtf(s2.w * inv - mu.w * mu.w + 1e-5f);

    float4* ob = reinterpret_cast<float4*>(out + (long long)b * (FEAT * NPTS)) + o4;
#pragma unroll 8
    for (int l = 0; l < FEAT; l++) {
        float4 v = base[l * (NPTS / 4)];
        float g = gamma[l], be = beta[l];
        float4 r;
        r.x = (v.x - mu.x) * rs.x * g + be;
        r.y = (v.y - mu.y) * rs.y * g + be;
        r.z = (v.z - mu.z) * rs.z * g + be;
        r.w = (v.w - mu.w) * rs.w * g + be;
        ob[l * (NPTS / 4)] = r;
    }
}

// ---------------- launch ----------------
extern "C" void kernel_launch(void* const* d_in, const int* in_sizes, int n_in,
                              void* d_out, int out_size)
{
    const float* query   = (const float*)d_in[0];
    const float* support = (const float*)d_in[1];
    const float* Wq      = (const float*)d_in[2];
    const float* Wk      = (const float*)d_in[3];
    const float* Wv      = (const float*)d_in[4];
    const float* gamma   = (const float*)d_in[5];
    const float* beta    = (const float*)d_in[6];
    float* out = (float*)d_out;

    void* sp = nullptr;
    cudaGetSymbolAddress(&sp, g_scratch);
    char* S = (char*)sp;
    __half* suph = (__half*)(S + O_SUPH);
    __half* qryh = (__half*)(S + O_QRYH);
    __half* wqh  = (__half*)(S + O_WQH);
    __half* wkh  = (__half*)(S + O_WKH);
    __half* wvh  = (__half*)(S + O_WVH);
    __half* qT   = (__half*)(S + O_QTH);
    __half* kT   = (__half*)(S + O_KTH);
    __half* vN   = (__half*)(S + O_VNH);
    float*  atf  = (float*)(S + O_ATF);
    __half* prh  = (__half*)(S + O_PRH);
    float*  tpf  = (float*)(S + O_TMPF);

    const long long sXh = (long long)FEAT * NPTS;     // 655360 (halfs)
    const long long sAt = (long long)FEAT * FEAT;     // 102400

    static bool attr_set = false;
    if (!attr_set) {
        cudaFuncSetAttribute(qkv_kernel,
                             cudaFuncAttributeMaxDynamicSharedMemorySize, SMEM_TOTAL_BYTES);
        cudaFuncSetAttribute(gemm_h_kernel<OM_F32A>,
                             cudaFuncAttributeMaxDynamicSharedMemorySize, SMEM_TOTAL_BYTES);
        cudaFuncSetAttribute(gemm_h_kernel<OM_F32RES>,
                             cudaFuncAttributeMaxDynamicSharedMemorySize, SMEM_TOTAL_BYTES);
        attr_set = true;
    }

    const size_t smb = SMEM_TOTAL_BYTES;
    const float alpha = 1.0f / sqrtf((float)FEAT);

    // single fused fp32->fp16 convert (support, query, Wq, Wk, Wv)
    cvt_all_kernel<<<CVT_B4 / 4 / 256, 256>>>(
        support, query, Wq, Wk, Wv, suph, qryh, wqh, wkh, wvh);

    // fused persistent QKV (flat 10240x2048x2048), vN transposed scatter
    qkv_kernel<<<296, 128, smb>>>(qryh, suph, wqh, wkh, wvh, qT, kT, vN);
    // attn logits fp32: M=N=320, K=2048
    gemm_h_kernel<OM_F32A><<<288, 128, smb>>>(
        qT, kT, (char*)atf, nullptr, 320, 320, 2048, 2048, 2048, 320,
        sXh, sXh, sAt, 0, alpha, 288, 3);
    // softmax -> fp16 probs
    softmax_kernel<<<dim3(FEAT, NB), 256>>>(atf, prh);
    // AV + residual: M=320, N=2048, K=320
    gemm_h_kernel<OM_F32RES><<<296, 128, smb>>>(
        prh, vN, (char*)tpf, query, 320, 2048, 320, 320, 320, 2048,
        sAt, sXh, sXh, sXh, 1.f, 1536, 16);
    // LayerNorm over l (FEAT), vectorized
    ln_kernel<<<dim3(NPTS / 4 / 256, NB), 256>>>(tpf, gamma, beta, out);
}

// round 10
// speedup vs baseline: 1.0303x; 1.0303x over previous
#include <cuda_runtime.h>
#include <cuda_fp16.h>
#include <cstdint>
#include <cmath>

#define NB 32
#define FEAT 320
#define NPTS 2048

static __device__ float g_scratch[87162880];   // 348 MB

// byte offsets into scratch
#define O_SUPH 0LL
#define O_QRYH 41943040LL
#define O_WQH  83886080LL
#define O_WKH  92274688LL
#define O_WVH  100663296LL
#define O_QTH  109051904LL
#define O_KTH  150994944LL
#define O_VNH  192937984LL
#define O_ATF  234881024LL
#define O_PRH  247988224LL
#define O_TMPF 254541824LL

#define STAGE_BYTES 32768          // A 16KB + B 16KB (fp16, BK=64)
#define SMEM_TOTAL_BYTES (3 * STAGE_BYTES)

#define OM_HALF   0
#define OM_TRANS  1
#define OM_F32A   2
#define OM_F32RES 3

// ---------------- PTX helpers ----------------
__device__ __forceinline__ uint32_t smem_u32(const void* p) {
    uint32_t a;
    asm("{ .reg .u64 t; cvta.to.shared.u64 t, %1; cvt.u32.u64 %0, t; }" : "=r"(a) : "l"(p));
    return a;
}

__device__ __forceinline__ void mma_f16(float* d, const uint32_t* a, const uint32_t* b) {
    asm volatile(
        "mma.sync.aligned.m16n8k16.row.col.f32.f16.f16.f32 "
        "{%0,%1,%2,%3}, {%4,%5,%6,%7}, {%8,%9}, {%0,%1,%2,%3};"
        : "+f"(d[0]), "+f"(d[1]), "+f"(d[2]), "+f"(d[3])
        : "r"(a[0]), "r"(a[1]), "r"(a[2]), "r"(a[3]), "r"(b[0]), "r"(b[1]));
}

__device__ __forceinline__ void ldsm4(uint32_t* r, uint32_t addr) {
    asm volatile("ldmatrix.sync.aligned.m8n8.x4.shared.b16 {%0,%1,%2,%3}, [%4];"
                 : "=r"(r[0]), "=r"(r[1]), "=r"(r[2]), "=r"(r[3]) : "r"(addr));
}

__device__ __forceinline__ void cpasync16(uint32_t dst, const void* src, bool pred) {
    int sz = pred ? 16 : 0;
    asm volatile("cp.async.cg.shared.global [%0], [%1], 16, %2;"
                 :: "r"(dst), "l"(src), "r"(sz) : "memory");
}
#define CP_COMMIT() asm volatile("cp.async.commit_group;" ::: "memory")
#define CP_WAIT1()  asm volatile("cp.async.wait_group 1;" ::: "memory")

// ---------------- fp16 tile core (register-pipelined) — unchanged from R8 ----------------
template<int OM>
__device__ __forceinline__ void run_tile_h(
    const __half* __restrict__ A, const __half* __restrict__ B,
    char* __restrict__ Cb, const float* __restrict__ D,
    int M, int N, int K, int lda, int ldb, int ldc, long long sCb,
    int bm, int bn, float alpha, uint32_t sb, char* smem)
{
    const int tid  = threadIdx.x;
    const int lane = tid & 31;
    const int warp = tid >> 5;
    const int wm = warp & 1;
    const int wn = warp >> 1;

    const int r0  = tid >> 3;          // 0..15
    const int seg = tid & 7;
    const uint32_t xorterm = (uint32_t)((seg ^ (r0 & 7)) << 4);

    const int mrowA = ((lane >> 3) & 1) * 8 + (lane & 7);
    const int khA   = lane >> 4;              // 0/1
    const int nrowB = (lane >> 4) * 8 + (lane & 7);
    const int khB   = (lane >> 3) & 1;
    uint32_t offA[4], phA[4], offB[4], phB[4];
#pragma unroll
    for (int mt = 0; mt < 4; mt++) {
        int rowA = wm * 64 + mt * 16 + mrowA;
        offA[mt] = (uint32_t)(rowA * 128);
        phA[mt]  = (uint32_t)(rowA & 7);
    }
#pragma unroll
    for (int np = 0; np < 4; np++) {
        int rowB = wn * 64 + np * 16 + nrowB;
        offB[np] = (uint32_t)(rowB * 128);
        phB[np]  = (uint32_t)(rowB & 7);
    }

    float acc[4][8][4];
#pragma unroll
    for (int i = 0; i < 4; i++)
#pragma unroll
        for (int j = 0; j < 8; j++)
#pragma unroll
            for (int r = 0; r < 4; r++) acc[i][j][r] = 0.f;

    const int NC = K >> 6;   // BK=64

    auto ISSUE = [&](int c) {
        const int k0 = c << 6;
        const uint32_t aB = sb + (uint32_t)((c % 3) * STAGE_BYTES);
        const uint32_t bB = aB + 16384;
#pragma unroll
        for (int i = 0; i < 8; i++) {
            int r = r0 + 16 * i;
            int gr = bm + r;
            bool p = gr < M;
            cpasync16(aB + (uint32_t)(r * 128) + xorterm,
                      A + (long long)(p ? gr : 0) * lda + k0 + seg * 8, p);
        }
#pragma unroll
        for (int i = 0; i < 8; i++) {
            int r = r0 + 16 * i;
            int gn = bn + r;
            bool p = gn < N;
            cpasync16(bB + (uint32_t)(r * 128) + xorterm,
                      B + (long long)(p ? gn : 0) * ldb + k0 + seg * 8, p);
        }
        CP_COMMIT();
    };

    uint32_t afr[2][4][4];
    uint32_t bfr[2][8][2];

    ISSUE(0);
    ISSUE(1);

    for (int c = 0; c < NC; c++) {
        CP_WAIT1();
        __syncthreads();

        const uint32_t aB = sb + (uint32_t)((c % 3) * STAGE_BYTES);
        const uint32_t bB = aB + 16384;

        {
            const uint32_t s16 = (uint32_t)khA;
#pragma unroll
            for (int mt = 0; mt < 4; mt++)
                ldsm4(afr[0][mt], aB + offA[mt] + ((s16 ^ phA[mt]) << 4));
        }
        {
            const uint32_t s16 = (uint32_t)khB;
#pragma unroll
            for (int np = 0; np < 4; np++) {
                uint32_t r[4];
                ldsm4(r, bB + offB[np] + ((s16 ^ phB[np]) << 4));
                bfr[0][2 * np][0] = r[0];     bfr[0][2 * np][1] = r[1];
                bfr[0][2 * np + 1][0] = r[2]; bfr[0][2 * np + 1][1] = r[3];
            }
        }

        if (c + 2 < NC) ISSUE(c + 2);
        else CP_COMMIT();

#pragma unroll
        for (int ks = 0; ks < 4; ks++) {
            const int cur = ks & 1;
            const int nxt = cur ^ 1;
            if (ks < 3) {
                const uint32_t sA16 = (uint32_t)(2 * (ks + 1) + khA);
#pragma unroll
                for (int mt = 0; mt < 4; mt++)
                    ldsm4(afr[nxt][mt], aB + offA[mt] + ((sA16 ^ phA[mt]) << 4));
                const uint32_t sB16 = (uint32_t)(2 * (ks + 1) + khB);
#pragma unroll
                for (int np = 0; np < 4; np++) {
                    uint32_t r[4];
                    ldsm4(r, bB + offB[np] + ((sB16 ^ phB[np]) << 4));
                    bfr[nxt][2 * np][0] = r[0];     bfr[nxt][2 * np][1] = r[1];
                    bfr[nxt][2 * np + 1][0] = r[2]; bfr[nxt][2 * np + 1][1] = r[3];
                }
            }
#pragma unroll
            for (int mt = 0; mt < 4; mt++)
#pragma unroll
                for (int nt = 0; nt < 8; nt++)
                    mma_f16(acc[mt][nt], afr[cur][mt], bfr[cur][nt]);
        }
    }

    // ---------------- epilogues ----------------
    if (OM == OM_HALF) {
        __half* C = (__half*)Cb;
#pragma unroll
        for (int mt = 0; mt < 4; mt++) {
#pragma unroll
            for (int nt = 0; nt < 8; nt++) {
                int row = bm + wm * 64 + mt * 16 + (lane >> 2);
                int col = bn + wn * 64 + nt * 8 + ((lane & 3) << 1);
                __half2 h0 = __float22half2_rn(make_float2(acc[mt][nt][0], acc[mt][nt][1]));
                __half2 h1 = __float22half2_rn(make_float2(acc[mt][nt][2], acc[mt][nt][3]));
                *reinterpret_cast<__half2*>(C + (long long)row * ldc + col) = h0;
                *reinterpret_cast<__half2*>(C + (long long)(row + 8) * ldc + col) = h1;
            }
        }
    } else if (OM == OM_F32A || OM == OM_F32RES) {
        float* C = (float*)Cb;
#pragma unroll
        for (int mt = 0; mt < 4; mt++) {
#pragma unroll
            for (int nt = 0; nt < 8; nt++) {
                int row = bm + wm * 64 + mt * 16 + (lane >> 2);
                int col = bn + wn * 64 + nt * 8 + ((lane & 3) << 1);
                if (col < N) {
                    if (row < M) {
                        long long i0 = (long long)row * ldc + col;
                        float2 v;
                        v.x = alpha * acc[mt][nt][0];
                        v.y = alpha * acc[mt][nt][1];
                        if (OM == OM_F32RES) { v.x += D[i0]; v.y += D[i0 + 1]; }
                        *reinterpret_cast<float2*>(C + i0) = v;
                    }
                    if (row + 8 < M) {
                        long long i1 = (long long)(row + 8) * ldc + col;
                        float2 v;
                        v.x = alpha * acc[mt][nt][2];
                        v.y = alpha * acc[mt][nt][3];
                        if (OM == OM_F32RES) { v.x += D[i1]; v.y += D[i1 + 1]; }
                        *reinterpret_cast<float2*>(C + i1) = v;
                    }
                }
            }
        }
    } else {   // OM_TRANS: scatter C[b][n][m%FEAT] as fp16 via smem staging
        float* Cs = reinterpret_cast<float*>(smem);
        __half* Ch = (__half*)Cb;
        __syncthreads();
#pragma unroll
        for (int mt = 0; mt < 4; mt++) {
#pragma unroll
            for (int nt = 0; nt < 8; nt++) {
                int nl = wn * 64 + nt * 8 + ((lane & 3) << 1);
                int m0 = wm * 64 + mt * 16 + (lane >> 2);
                Cs[nl * 132 + m0]           = acc[mt][nt][0];
                Cs[(nl + 1) * 132 + m0]     = acc[mt][nt][1];
                Cs[nl * 132 + m0 + 8]       = acc[mt][nt][2];
                Cs[(nl + 1) * 132 + m0 + 8] = acc[mt][nt][3];
            }
        }
        __syncthreads();
#pragma unroll
        for (int it = 0; it < 32; it++) {
            int linear = tid + it * 128;
            int row = linear >> 5;
            int c4  = linear & 31;
            int n_g = bn + row;
            int m_g = bm + c4 * 4;
            int bb  = m_g / FEAT;
            int mm  = m_g - bb * FEAT;
            float4 v = *reinterpret_cast<const float4*>(&Cs[row * 132 + c4 * 4]);
            __half2 h0 = __float22half2_rn(make_float2(v.x, v.y));
            __half2 h1 = __float22half2_rn(make_float2(v.z, v.w));
            __half2* dst = reinterpret_cast<__half2*>(
                Ch + (long long)bb * sCb + (long long)n_g * ldc + mm);
            dst[0] = h0; dst[1] = h1;
        }
    }
}

// ---------------- fused persistent QKV ----------------
#define QKV_TILES_PER_OP 1280
#define QKV_NTILES 3840

__global__ __launch_bounds__(128, 2)
void qkv_kernel(const __half* __restrict__ qryh, const __half* __restrict__ suph,
                const __half* __restrict__ wq, const __half* __restrict__ wk,
                const __half* __restrict__ wv,
                __half* __restrict__ qT, __half* __restrict__ kT, __half* __restrict__ vN)
{
    extern __shared__ char smem[];
    const uint32_t sb = smem_u32(smem);
    const long long sX = (long long)FEAT * NPTS;

    for (int t = blockIdx.x; t < QKV_NTILES; t += gridDim.x) {
        int op = t / QKV_TILES_PER_OP;
        int r  = t - op * QKV_TILES_PER_OP;
        int bm = (r >> 4) * 128;
        int bn = (r & 15) * 128;
        __syncthreads();
        if (op == 0) {
            run_tile_h<OM_HALF>(suph, wq, (char*)qT, nullptr,
                                NB * FEAT, 2048, 2048, 2048, 2048, 2048, 0,
                                bm, bn, 1.f, sb, smem);
        } else if (op == 1) {
            run_tile_h<OM_HALF>(qryh, wk, (char*)kT, nullptr,
                                NB * FEAT, 2048, 2048, 2048, 2048, 2048, 0,
                                bm, bn, 1.f, sb, smem);
        } else {
            run_tile_h<OM_TRANS>(qryh, wv, (char*)vN, nullptr,
                                 NB * FEAT, 2048, 2048, 2048, 2048, 320, sX,
                                 bm, bn, 1.f, sb, smem);
        }
    }
}

// ---------------- generic persistent batched GEMM (fp16 in) ----------------
template<int OM>
__global__ __launch_bounds__(128, 2)
void gemm_h_kernel(const __half* __restrict__ Ag, const __half* __restrict__ Bg,
                   char* __restrict__ Cg, const float* __restrict__ Dg,
                   int M, int N, int K, int lda, int ldb, int ldc,
                   long long sA, long long sB, long long sC, long long sD,
                   float alpha, int ntiles, int tn)
{
    extern __shared__ char smem[];
    const uint32_t sb = smem_u32(smem);
    const int per = ((M + 127) >> 7) * tn;
    const int esz = (OM == OM_HALF || OM == OM_TRANS) ? 2 : 4;

    for (int t = blockIdx.x; t < ntiles; t += gridDim.x) {
        int b = t / per;
        int r = t - b * per;
        int bm = (r / tn) * 128;
        int bn = (r % tn) * 128;
        __syncthreads();
        run_tile_h<OM>(Ag + (long long)b * sA, Bg + (long long)b * sB,
                       Cg + (long long)b * sC * esz,
                       Dg ? (Dg + (long long)b * sD) : nullptr,
                       M, N, K, lda, ldb, ldc, 0, bm, bn, alpha, sb, smem);
    }
}

// ---------------- fused convert: coalesced + MLP=4 ----------------
// Each 256-thread block owns 1024 consecutive float4 units; 4 iterations of
// (tid + i*256) keep every load lane-contiguous. Region boundaries are all
// multiples of 1024 float4, so the region decode is per-block.
#define CVT_B0 5242880
#define CVT_B1 10485760
#define CVT_B2 11534336
#define CVT_B3 12582912
#define CVT_B4 13631488

__global__ __launch_bounds__(256) void cvt_all_kernel(
    const float* __restrict__ s,  const float* __restrict__ q,
    const float* __restrict__ w0, const float* __restrict__ w1, const float* __restrict__ w2,
    __half* __restrict__ sh, __half* __restrict__ qh,
    __half* __restrict__ h0, __half* __restrict__ h1, __half* __restrict__ h2)
{
    long long blk = (long long)blockIdx.x * 1024;
    const float* src; __half* dst; long long off0;
    if (blk < CVT_B0)      { src = s;  dst = sh; off0 = blk; }
    else if (blk < CVT_B1) { src = q;  dst = qh; off0 = blk - CVT_B0; }
    else if (blk < CVT_B2) { src = w0; dst = h0; off0 = blk - CVT_B1; }
    else if (blk < CVT_B3) { src = w1; dst = h1; off0 = blk - CVT_B2; }
    else                   { src = w2; dst = h2; off0 = blk - CVT_B3; }
    off0 += threadIdx.x;
    float4 v[4];
#pragma unroll
    for (int i = 0; i < 4; i++)
        v[i] = reinterpret_cast<const float4*>(src)[off0 + i * 256];
#pragma unroll
    for (int i = 0; i < 4; i++) {
        __half2 a = __float22half2_rn(make_float2(v[i].x, v[i].y));
        __half2 b = __float22half2_rn(make_float2(v[i].z, v[i].w));
        uint2 u;
        u.x = *reinterpret_cast<uint32_t*>(&a);
        u.y = *reinterpret_cast<uint32_t*>(&b);
        reinterpret_cast<uint2*>(dst)[off0 + i * 256] = u;
    }
}

// ---------------- warp-per-row softmax ----------------
// 10240 rows of 320 fp32 logits -> fp16 probs. 8 warps/block, 1 row/warp,
// lane-strided access (coalesced), shfl reductions, no __syncthreads.
__global__ __launch_bounds__(256) void softmax_kernel(const float* __restrict__ attn,
                                                      __half* __restrict__ probs)
{
    const int lane = threadIdx.x & 31;
    const int wrow = (blockIdx.x << 3) + (threadIdx.x >> 5);
    const float* row = attn + (long long)wrow * FEAT;

    float v[10];
    float m = -1e30f;
#pragma unroll
    for (int j = 0; j < 10; j++) {
        v[j] = row[lane + 32 * j];
        m = fmaxf(m, v[j]);
    }
#pragma unroll
    for (int s = 16; s > 0; s >>= 1)
        m = fmaxf(m, __shfl_xor_sync(0xffffffff, m, s));
    float sum = 0.f;
#pragma unroll
    for (int j = 0; j < 10; j++) {
        v[j] = expf(v[j] - m);
        sum += v[j];
    }
#pragma unroll
    for (int s = 16; s > 0; s >>= 1)
        sum += __shfl_xor_sync(0xffffffff, sum, s);
    float inv = 1.f / sum;
    __half* orow = probs + (long long)wrow * FEAT;
#pragma unroll
    for (int j = 0; j < 10; j++)
        orow[lane + 32 * j] = __float2half(v[j] * inv);
}

// ---------------- vectorized LayerNorm (float4 columns, MLP-8) ----------------
__global__ __launch_bounds__(256) void ln_kernel(const float* __restrict__ tp,
                                                 const float* __restrict__ gamma,
                                                 const float* __restrict__ beta,
                                                 float* __restrict__ out)
{
    const int b  = blockIdx.y;
    const int o4 = blockIdx.x * 256 + threadIdx.x;
    const float4* base = reinterpret_cast<const float4*>(tp + (long long)b * (FEAT * NPTS)) + o4;

    float4 s  = make_float4(0.f, 0.f, 0.f, 0.f);
    float4 s2 = make_float4(0.f, 0.f, 0.f, 0.f);
#pragma unroll 8
    for (int l = 0; l < FEAT; l++) {
        float4 v = base[l * (NPTS / 4)];
        s.x += v.x;  s.y += v.y;  s.z += v.z;  s.w += v.w;
        s2.x += v.x * v.x;  s2.y += v.y * v.y;  s2.z += v.z * v.z;  s2.w += v.w * v.w;
    }
    const float inv = 1.f / FEAT;
    float4 mu = make_float4(s.x * inv, s.y * inv, s.z * inv, s.w * inv);
    float4 rs;
    rs.x = rsqrtf(s2.x * inv - mu.x * mu.x + 1e-5f);
    rs.y = rsqrtf(s2.y * inv - mu.y * mu.y + 1e-5f);
    rs.z = rsqrtf(s2.z * inv - mu.z * mu.z + 1e-5f);
    rs.w = rsqrtf(s2.w * inv - mu.w * mu.w + 1e-5f);

    float4* ob = reinterpret_cast<float4*>(out + (long long)b * (FEAT * NPTS)) + o4;
#pragma unroll 8
    for (int l = 0; l < FEAT; l++) {
        float4 v = base[l * (NPTS / 4)];
        float g = gamma[l], be = beta[l];
        float4 r;
        r.x = (v.x - mu.x) * rs.x * g + be;
        r.y = (v.y - mu.y) * rs.y * g + be;
        r.z = (v.z - mu.z) * rs.z * g + be;
        r.w = (v.w - mu.w) * rs.w * g + be;
        ob[l * (NPTS / 4)] = r;
    }
}

// ---------------- launch ----------------
extern "C" void kernel_launch(void* const* d_in, const int* in_sizes, int n_in,
                              void* d_out, int out_size)
{
    const float* query   = (const float*)d_in[0];
    const float* support = (const float*)d_in[1];
    const float* Wq      = (const float*)d_in[2];
    const float* Wk      = (const float*)d_in[3];
    const float* Wv      = (const float*)d_in[4];
    const float* gamma   = (const float*)d_in[5];
    const float* beta    = (const float*)d_in[6];
    float* out = (float*)d_out;

    void* sp = nullptr;
    cudaGetSymbolAddress(&sp, g_scratch);
    char* S = (char*)sp;
    __half* suph = (__half*)(S + O_SUPH);
    __half* qryh = (__half*)(S + O_QRYH);
    __half* wqh  = (__half*)(S + O_WQH);
    __half* wkh  = (__half*)(S + O_WKH);
    __half* wvh  = (__half*)(S + O_WVH);
    __half* qT   = (__half*)(S + O_QTH);
    __half* kT   = (__half*)(S + O_KTH);
    __half* vN   = (__half*)(S + O_VNH);
    float*  atf  = (float*)(S + O_ATF);
    __half* prh  = (__half*)(S + O_PRH);
    float*  tpf  = (float*)(S + O_TMPF);

    const long long sXh = (long long)FEAT * NPTS;     // 655360 (halfs)
    const long long sAt = (long long)FEAT * FEAT;     // 102400

    static bool attr_set = false;
    if (!attr_set) {
        cudaFuncSetAttribute(qkv_kernel,
                             cudaFuncAttributeMaxDynamicSharedMemorySize, SMEM_TOTAL_BYTES);
        cudaFuncSetAttribute(gemm_h_kernel<OM_F32A>,
                             cudaFuncAttributeMaxDynamicSharedMemorySize, SMEM_TOTAL_BYTES);
        cudaFuncSetAttribute(gemm_h_kernel<OM_F32RES>,
                             cudaFuncAttributeMaxDynamicSharedMemorySize, SMEM_TOTAL_BYTES);
        attr_set = true;
    }

    const size_t smb = SMEM_TOTAL_BYTES;
    const float alpha = 1.0f / sqrtf((float)FEAT);

    // fused fp32->fp16 convert, coalesced + MLP=4 (block = 1024 float4)
    cvt_all_kernel<<<CVT_B4 / 1024, 256>>>(
        support, query, Wq, Wk, Wv, suph, qryh, wqh, wkh, wvh);

    // fused persistent QKV (flat 10240x2048x2048), vN transposed scatter
    qkv_kernel<<<296, 128, smb>>>(qryh, suph, wqh, wkh, wvh, qT, kT, vN);
    // attn logits fp32: M=N=320, K=2048
    gemm_h_kernel<OM_F32A><<<288, 128, smb>>>(
        qT, kT, (char*)atf, nullptr, 320, 320, 2048, 2048, 2048, 320,
        sXh, sXh, sAt, 0, alpha, 288, 3);
    // warp-per-row softmax -> fp16 probs (10240 rows, 8 rows/block)
    softmax_kernel<<<NB * FEAT / 8, 256>>>(atf, prh);
    // AV + residual: M=320, N=2048, K=320
    gemm_h_kernel<OM_F32RES><<<296, 128, smb>>>(
        prh, vN, (char*)tpf, query, 320, 2048, 320, 320, 320, 2048,
        sAt, sXh, sXh, sXh, 1.f, 1536, 16);
    // LayerNorm over l (FEAT), vectorized
    ln_kernel<<<dim3(NPTS / 4 / 256, NB), 256>>>(tpf, gamma, beta, out);
}

// round 11
// speedup vs baseline: 1.0590x; 1.0279x over previous
#include <cuda_runtime.h>
#include <cuda_fp16.h>
#include <cstdint>
#include <cmath>

#define NB 32
#define FEAT 320
#define NPTS 2048

static __device__ float g_scratch[87162880];   // 348 MB

// byte offsets into scratch
#define O_SUPH 0LL
#define O_QRYH 41943040LL
#define O_WQH  83886080LL
#define O_WKH  92274688LL
#define O_WVH  100663296LL
#define O_QTH  109051904LL
#define O_KTH  150994944LL
#define O_VNH  192937984LL
#define O_ATF  234881024LL
#define O_PRH  247988224LL
#define O_TMPF 254541824LL

#define STAGE_BYTES 32768           // 128-core: A 16KB + B 16KB
#define SMEM_TOTAL_BYTES (3 * STAGE_BYTES)

#define STAGE2_BYTES 49152          // 256-core: A 32KB + B 16KB
#define SMEM2_TOTAL_BYTES (3 * STAGE2_BYTES)   // 147456; also covers TRANS staging (133KB)

#define OM_HALF   0
#define OM_TRANS  1
#define OM_F32A   2
#define OM_F32RES 3

// ---------------- PTX helpers ----------------
__device__ __forceinline__ uint32_t smem_u32(const void* p) {
    uint32_t a;
    asm("{ .reg .u64 t; cvta.to.shared.u64 t, %1; cvt.u32.u64 %0, t; }" : "=r"(a) : "l"(p));
    return a;
}

__device__ __forceinline__ void mma_f16(float* d, const uint32_t* a, const uint32_t* b) {
    asm volatile(
        "mma.sync.aligned.m16n8k16.row.col.f32.f16.f16.f32 "
        "{%0,%1,%2,%3}, {%4,%5,%6,%7}, {%8,%9}, {%0,%1,%2,%3};"
        : "+f"(d[0]), "+f"(d[1]), "+f"(d[2]), "+f"(d[3])
        : "r"(a[0]), "r"(a[1]), "r"(a[2]), "r"(a[3]), "r"(b[0]), "r"(b[1]));
}

__device__ __forceinline__ void ldsm4(uint32_t* r, uint32_t addr) {
    asm volatile("ldmatrix.sync.aligned.m8n8.x4.shared.b16 {%0,%1,%2,%3}, [%4];"
                 : "=r"(r[0]), "=r"(r[1]), "=r"(r[2]), "=r"(r[3]) : "r"(addr));
}

__device__ __forceinline__ void cpasync16(uint32_t dst, const void* src, bool pred) {
    int sz = pred ? 16 : 0;
    asm volatile("cp.async.cg.shared.global [%0], [%1], 16, %2;"
                 :: "r"(dst), "l"(src), "r"(sz) : "memory");
}
#define CP_COMMIT() asm volatile("cp.async.commit_group;" ::: "memory")
#define CP_WAIT1()  asm volatile("cp.async.wait_group 1;" ::: "memory")

// ================= 128x128 tile core (R8-proven) — used by attn / AV =================
template<int OM>
__device__ __forceinline__ void run_tile_h(
    const __half* __restrict__ A, const __half* __restrict__ B,
    char* __restrict__ Cb, const float* __restrict__ D,
    int M, int N, int K, int lda, int ldb, int ldc,
    int bm, int bn, float alpha, uint32_t sb)
{
    const int tid  = threadIdx.x;
    const int lane = tid & 31;
    const int warp = tid >> 5;
    const int wm = warp & 1;
    const int wn = warp >> 1;

    const int r0  = tid >> 3;
    const int seg = tid & 7;
    const uint32_t xorterm = (uint32_t)((seg ^ (r0 & 7)) << 4);

    const int mrowA = ((lane >> 3) & 1) * 8 + (lane & 7);
    const int khA   = lane >> 4;
    const int nrowB = (lane >> 4) * 8 + (lane & 7);
    const int khB   = (lane >> 3) & 1;
    uint32_t offA[4], phA[4], offB[4], phB[4];
#pragma unroll
    for (int mt = 0; mt < 4; mt++) {
        int rowA = wm * 64 + mt * 16 + mrowA;
        offA[mt] = (uint32_t)(rowA * 128);
        phA[mt]  = (uint32_t)(rowA & 7);
    }
#pragma unroll
    for (int np = 0; np < 4; np++) {
        int rowB = wn * 64 + np * 16 + nrowB;
        offB[np] = (uint32_t)(rowB * 128);
        phB[np]  = (uint32_t)(rowB & 7);
    }

    float acc[4][8][4];
#pragma unroll
    for (int i = 0; i < 4; i++)
#pragma unroll
        for (int j = 0; j < 8; j++)
#pragma unroll
            for (int r = 0; r < 4; r++) acc[i][j][r] = 0.f;

    const int NC = K >> 6;

    auto ISSUE = [&](int c) {
        const int k0 = c << 6;
        const uint32_t aB = sb + (uint32_t)((c % 3) * STAGE_BYTES);
        const uint32_t bB = aB + 16384;
#pragma unroll
        for (int i = 0; i < 8; i++) {
            int r = r0 + 16 * i;
            int gr = bm + r;
            bool p = gr < M;
            cpasync16(aB + (uint32_t)(r * 128) + xorterm,
                      A + (long long)(p ? gr : 0) * lda + k0 + seg * 8, p);
        }
#pragma unroll
        for (int i = 0; i < 8; i++) {
            int r = r0 + 16 * i;
            int gn = bn + r;
            bool p = gn < N;
            cpasync16(bB + (uint32_t)(r * 128) + xorterm,
                      B + (long long)(p ? gn : 0) * ldb + k0 + seg * 8, p);
        }
        CP_COMMIT();
    };

    uint32_t afr[2][4][4];
    uint32_t bfr[2][8][2];

    ISSUE(0);
    ISSUE(1);

    for (int c = 0; c < NC; c++) {
        CP_WAIT1();
        __syncthreads();

        const uint32_t aB = sb + (uint32_t)((c % 3) * STAGE_BYTES);
        const uint32_t bB = aB + 16384;

        {
            const uint32_t s16 = (uint32_t)khA;
#pragma unroll
            for (int mt = 0; mt < 4; mt++)
                ldsm4(afr[0][mt], aB + offA[mt] + ((s16 ^ phA[mt]) << 4));
        }
        {
            const uint32_t s16 = (uint32_t)khB;
#pragma unroll
            for (int np = 0; np < 4; np++) {
                uint32_t r[4];
                ldsm4(r, bB + offB[np] + ((s16 ^ phB[np]) << 4));
                bfr[0][2 * np][0] = r[0];     bfr[0][2 * np][1] = r[1];
                bfr[0][2 * np + 1][0] = r[2]; bfr[0][2 * np + 1][1] = r[3];
            }
        }

        if (c + 2 < NC) ISSUE(c + 2);
        else CP_COMMIT();

#pragma unroll
        for (int ks = 0; ks < 4; ks++) {
            const int cur = ks & 1;
            const int nxt = cur ^ 1;
            if (ks < 3) {
                const uint32_t sA16 = (uint32_t)(2 * (ks + 1) + khA);
#pragma unroll
                for (int mt = 0; mt < 4; mt++)
                    ldsm4(afr[nxt][mt], aB + offA[mt] + ((sA16 ^ phA[mt]) << 4));
                const uint32_t sB16 = (uint32_t)(2 * (ks + 1) + khB);
#pragma unroll
                for (int np = 0; np < 4; np++) {
                    uint32_t r[4];
                    ldsm4(r, bB + offB[np] + ((sB16 ^ phB[np]) << 4));
                    bfr[nxt][2 * np][0] = r[0];     bfr[nxt][2 * np][1] = r[1];
                    bfr[nxt][2 * np + 1][0] = r[2]; bfr[nxt][2 * np + 1][1] = r[3];
                }
            }
#pragma unroll
            for (int mt = 0; mt < 4; mt++)
#pragma unroll
                for (int nt = 0; nt < 8; nt++)
                    mma_f16(acc[mt][nt], afr[cur][mt], bfr[cur][nt]);
        }
    }

    // epilogues (f32 variants only used here)
    float* C = (float*)Cb;
#pragma unroll
    for (int mt = 0; mt < 4; mt++) {
#pragma unroll
        for (int nt = 0; nt < 8; nt++) {
            int row = bm + wm * 64 + mt * 16 + (lane >> 2);
            int col = bn + wn * 64 + nt * 8 + ((lane & 3) << 1);
            if (col < N) {
                if (row < M) {
                    long long i0 = (long long)row * ldc + col;
                    float2 v;
                    v.x = alpha * acc[mt][nt][0];
                    v.y = alpha * acc[mt][nt][1];
                    if (OM == OM_F32RES) { v.x += D[i0]; v.y += D[i0 + 1]; }
                    *reinterpret_cast<float2*>(C + i0) = v;
                }
                if (row + 8 < M) {
                    long long i1 = (long long)(row + 8) * ldc + col;
                    float2 v;
                    v.x = alpha * acc[mt][nt][2];
                    v.y = alpha * acc[mt][nt][3];
                    if (OM == OM_F32RES) { v.x += D[i1]; v.y += D[i1 + 1]; }
                    *reinterpret_cast<float2*>(C + i1) = v;
                }
            }
        }
    }
}

template<int OM>
__global__ __launch_bounds__(128, 2)
void gemm_h_kernel(const __half* __restrict__ Ag, const __half* __restrict__ Bg,
                   char* __restrict__ Cg, const float* __restrict__ Dg,
                   int M, int N, int K, int lda, int ldb, int ldc,
                   long long sA, long long sB, long long sC, long long sD,
                   float alpha, int ntiles, int tn)
{
    extern __shared__ char smem[];
    const uint32_t sb = smem_u32(smem);
    const int per = ((M + 127) >> 7) * tn;

    for (int t = blockIdx.x; t < ntiles; t += gridDim.x) {
        int b = t / per;
        int r = t - b * per;
        int bm = (r / tn) * 128;
        int bn = (r % tn) * 128;
        __syncthreads();
        run_tile_h<OM>(Ag + (long long)b * sA, Bg + (long long)b * sB,
                       Cg + (long long)b * sC * 4,
                       Dg ? (Dg + (long long)b * sD) : nullptr,
                       M, N, K, lda, ldb, ldc, bm, bn, alpha, sb);
    }
}

// ================= 256x128 tile core — QKV only (M=10240, N=2048, K=2048) =================
// 256 threads, warps 4m x 2n, warp tile 64x64, BK=64, 3-stage cp.async,
// 2-stage register fragment pipeline. No M/N predicates (always in range).
template<bool TRANSC>
__device__ __forceinline__ void run_tile_q(
    const __half* __restrict__ A, const __half* __restrict__ B,
    __half* __restrict__ C, int ldc, long long sCb,
    int bm, int bn, uint32_t sb, char* smem)
{
    const int tid  = threadIdx.x;
    const int lane = tid & 31;
    const int warp = tid >> 5;
    const int wm = warp >> 1;       // 0..3
    const int wn = warp & 1;        // 0..1

    const int r0  = tid >> 3;       // 0..31
    const int seg = tid & 7;
    const uint32_t xorterm = (uint32_t)((seg ^ (r0 & 7)) << 4);

    const int mrowA = ((lane >> 3) & 1) * 8 + (lane & 7);
    const int khA   = lane >> 4;
    const int nrowB = (lane >> 4) * 8 + (lane & 7);
    const int khB   = (lane >> 3) & 1;
    uint32_t offA[4], phA[4], offB[4], phB[4];
#pragma unroll
    for (int mt = 0; mt < 4; mt++) {
        int rowA = wm * 64 + mt * 16 + mrowA;      // < 256
        offA[mt] = (uint32_t)(rowA * 128);
        phA[mt]  = (uint32_t)(rowA & 7);
    }
#pragma unroll
    for (int np = 0; np < 4; np++) {
        int rowB = wn * 64 + np * 16 + nrowB;      // < 128
        offB[np] = (uint32_t)(rowB * 128);
        phB[np]  = (uint32_t)(rowB & 7);
    }

    float acc[4][8][4];
#pragma unroll
    for (int i = 0; i < 4; i++)
#pragma unroll
        for (int j = 0; j < 8; j++)
#pragma unroll
            for (int r = 0; r < 4; r++) acc[i][j][r] = 0.f;

    const int NC = 2048 >> 6;   // 32

    auto ISSUE = [&](int c) {
        const int k0 = c << 6;
        const uint32_t aB = sb + (uint32_t)((c % 3) * STAGE2_BYTES);
        const uint32_t bB = aB + 32768;
#pragma unroll
        for (int i = 0; i < 8; i++) {               // A: 256 rows
            int r = r0 + 32 * i;
            cpasync16(aB + (uint32_t)(r * 128) + xorterm,
                      A + (long long)(bm + r) * 2048 + k0 + seg * 8, true);
        }
#pragma unroll
        for (int i = 0; i < 4; i++) {               // B: 128 rows
            int r = r0 + 32 * i;
            cpasync16(bB + (uint32_t)(r * 128) + xorterm,
                      B + (long long)(bn + r) * 2048 + k0 + seg * 8, true);
        }
        CP_COMMIT();
    };

    uint32_t afr[2][4][4];
    uint32_t bfr[2][8][2];

    ISSUE(0);
    ISSUE(1);

    for (int c = 0; c < NC; c++) {
        CP_WAIT1();
        __syncthreads();

        const uint32_t aB = sb + (uint32_t)((c % 3) * STAGE2_BYTES);
        const uint32_t bB = aB + 32768;

        {
            const uint32_t s16 = (uint32_t)khA;
#pragma unroll
            for (int mt = 0; mt < 4; mt++)
                ldsm4(afr[0][mt], aB + offA[mt] + ((s16 ^ phA[mt]) << 4));
        }
        {
            const uint32_t s16 = (uint32_t)khB;
#pragma unroll
            for (int np = 0; np < 4; np++) {
                uint32_t r[4];
                ldsm4(r, bB + offB[np] + ((s16 ^ phB[np]) << 4));
                bfr[0][2 * np][0] = r[0];     bfr[0][2 * np][1] = r[1];
                bfr[0][2 * np + 1][0] = r[2]; bfr[0][2 * np + 1][1] = r[3];
            }
        }

        if (c + 2 < NC) ISSUE(c + 2);
        else CP_COMMIT();

#pragma unroll
        for (int ks = 0; ks < 4; ks++) {
            const int cur = ks & 1;
            const int nxt = cur ^ 1;
            if (ks < 3) {
                const uint32_t sA16 = (uint32_t)(2 * (ks + 1) + khA);
#pragma unroll
                for (int mt = 0; mt < 4; mt++)
                    ldsm4(afr[nxt][mt], aB + offA[mt] + ((sA16 ^ phA[mt]) << 4));
                const uint32_t sB16 = (uint32_t)(2 * (ks + 1) + khB);
#pragma unroll
                for (int np = 0; np < 4; np++) {
                    uint32_t r[4];
                    ldsm4(r, bB + offB[np] + ((sB16 ^ phB[np]) << 4));
                    bfr[nxt][2 * np][0] = r[0];     bfr[nxt][2 * np][1] = r[1];
                    bfr[nxt][2 * np + 1][0] = r[2]; bfr[nxt][2 * np + 1][1] = r[3];
                }
            }
#pragma unroll
            for (int mt = 0; mt < 4; mt++)
#pragma unroll
                for (int nt = 0; nt < 8; nt++)
                    mma_f16(acc[mt][nt], afr[cur][mt], bfr[cur][nt]);
        }
    }

    if (!TRANSC) {
        // direct fp16 store: C[row][col], row = flat m, col = n
#pragma unroll
        for (int mt = 0; mt < 4; mt++) {
#pragma unroll
            for (int nt = 0; nt < 8; nt++) {
                int row = bm + wm * 64 + mt * 16 + (lane >> 2);
                int col = bn + wn * 64 + nt * 8 + ((lane & 3) << 1);
                __half2 h0 = __float22half2_rn(make_float2(acc[mt][nt][0], acc[mt][nt][1]));
                __half2 h1 = __float22half2_rn(make_float2(acc[mt][nt][2], acc[mt][nt][3]));
                *reinterpret_cast<__half2*>(C + (long long)row * ldc + col) = h0;
                *reinterpret_cast<__half2*>(C + (long long)(row + 8) * ldc + col) = h1;
            }
        }
    } else {
        // transposed scatter via smem staging: Cs[128 n][260 m-floats]
        float* Cs = reinterpret_cast<float*>(smem);
        __syncthreads();
#pragma unroll
        for (int mt = 0; mt < 4; mt++) {
#pragma unroll
            for (int nt = 0; nt < 8; nt++) {
                int nl = wn * 64 + nt * 8 + ((lane & 3) << 1);
                int m0 = wm * 64 + mt * 16 + (lane >> 2);
                Cs[nl * 260 + m0]           = acc[mt][nt][0];
                Cs[(nl + 1) * 260 + m0]     = acc[mt][nt][1];
                Cs[nl * 260 + m0 + 8]       = acc[mt][nt][2];
                Cs[(nl + 1) * 260 + m0 + 8] = acc[mt][nt][3];
            }
        }
        __syncthreads();
#pragma unroll
        for (int it = 0; it < 32; it++) {
            int linear = tid + it * 256;
            int row = linear >> 6;          // local n 0..127
            int c4  = linear & 63;          // float4 group along m (256/4)
            int n_g = bn + row;
            int m_g = bm + c4 * 4;          // flat m
            int bb  = m_g / FEAT;
            int mm  = m_g - bb * FEAT;
            float4 v = *reinterpret_cast<const float4*>(&Cs[row * 260 + c4 * 4]);
            __half2 h0 = __float22half2_rn(make_float2(v.x, v.y));
            __half2 h1 = __float22half2_rn(make_float2(v.z, v.w));
            __half2* dst = reinterpret_cast<__half2*>(
                C + (long long)bb * sCb + (long long)n_g * ldc + mm);
            dst[0] = h0; dst[1] = h1;
        }
    }
}

// persistent fused QKV: 3 ops x 640 tiles (40 bm x 16 bn), grid 148
#define QKV2_PER_OP 640
#define QKV2_NTILES 1920

__global__ __launch_bounds__(256, 1)
void qkv_kernel(const __half* __restrict__ qryh, const __half* __restrict__ suph,
                const __half* __restrict__ wq, const __half* __restrict__ wk,
                const __half* __restrict__ wv,
                __half* __restrict__ qT, __half* __restrict__ kT, __half* __restrict__ vN)
{
    extern __shared__ char smem[];
    const uint32_t sb = smem_u32(smem);
    const long long sX = (long long)FEAT * NPTS;

    for (int t = blockIdx.x; t < QKV2_NTILES; t += gridDim.x) {
        int op = t / QKV2_PER_OP;
        int r  = t - op * QKV2_PER_OP;
        int bm = (r >> 4) * 256;
        int bn = (r & 15) * 128;
        __syncthreads();
        if (op == 0)      run_tile_q<false>(suph, wq, qT, 2048, 0,  bm, bn, sb, smem);
        else if (op == 1) run_tile_q<false>(qryh, wk, kT, 2048, 0,  bm, bn, sb, smem);
        else              run_tile_q<true >(qryh, wv, vN, 320,  sX, bm, bn, sb, smem);
    }
}

// ---------------- converts (R8-style, 5 launches) ----------------
__global__ __launch_bounds__(256) void f2h_kernel(const float* __restrict__ in,
                                                  __half* __restrict__ out, int n4)
{
    int i = blockIdx.x * 256 + threadIdx.x;
    if (i < n4) {
        float4 v = reinterpret_cast<const float4*>(in)[i];
        __half2 h0 = __float22half2_rn(make_float2(v.x, v.y));
        __half2 h1 = __float22half2_rn(make_float2(v.z, v.w));
        reinterpret_cast<__half2*>(out)[2 * i]     = h0;
        reinterpret_cast<__half2*>(out)[2 * i + 1] = h1;
    }
}

// ---------------- warp-per-row softmax (R10, measured 7.7us) ----------------
__global__ __launch_bounds__(256) void softmax_kernel(const float* __restrict__ attn,
                                                      __half* __restrict__ probs)
{
    const int lane = threadIdx.x & 31;
    const int wrow = (blockIdx.x << 3) + (threadIdx.x >> 5);
    const float* row = attn + (long long)wrow * FEAT;

    float v[10];
    float m = -1e30f;
#pragma unroll
    for (int j = 0; j < 10; j++) {
        v[j] = row[lane + 32 * j];
        m = fmaxf(m, v[j]);
    }
#pragma unroll
    for (int s = 16; s > 0; s >>= 1)
        m = fmaxf(m, __shfl_xor_sync(0xffffffff, m, s));
    float sum = 0.f;
#pragma unroll
    for (int j = 0; j < 10; j++) {
        v[j] = expf(v[j] - m);
        sum += v[j];
    }
#pragma unroll
    for (int s = 16; s > 0; s >>= 1)
        sum += __shfl_xor_sync(0xffffffff, sum, s);
    float inv = 1.f / sum;
    __half* orow = probs + (long long)wrow * FEAT;
#pragma unroll
    for (int j = 0; j < 10; j++)
        orow[lane + 32 * j] = __float2half(v[j] * inv);
}

// ---------------- LayerNorm (R8 exact: 256 blocks, coalesced scalar columns) ----------------
__global__ __launch_bounds__(256) void ln_kernel(const float* __restrict__ tp,
                                                 const float* __restrict__ gamma,
                                                 const float* __restrict__ beta,
                                                 float* __restrict__ out)
{
    const int b = blockIdx.y;
    const int o = blockIdx.x * 256 + threadIdx.x;
    const float* base = tp + (long long)b * (FEAT * NPTS) + o;
    float s = 0.f, s2 = 0.f;
#pragma unroll 4
    for (int l = 0; l < FEAT; l++) {
        float v = base[(long long)l * NPTS];
        s += v;
        s2 += v * v;
    }
    const float inv = 1.f / FEAT;
    float mu = s * inv;
    float var = s2 * inv - mu * mu;
    float rstd = rsqrtf(var + 1e-5f);
    float* ob = out + (long long)b * (FEAT * NPTS) + o;
#pragma unroll 4
    for (int l = 0; l < FEAT; l++) {
        float v = base[(long long)l * NPTS];
        ob[(long long)l * NPTS] = (v - mu) * rstd * gamma[l] + beta[l];
    }
}

// ---------------- launch ----------------
extern "C" void kernel_launch(void* const* d_in, const int* in_sizes, int n_in,
                              void* d_out, int out_size)
{
    const float* query   = (const float*)d_in[0];
    const float* support = (const float*)d_in[1];
    const float* Wq      = (const float*)d_in[2];
    const float* Wk      = (const float*)d_in[3];
    const float* Wv      = (const float*)d_in[4];
    const float* gamma   = (const float*)d_in[5];
    const float* beta    = (const float*)d_in[6];
    float* out = (float*)d_out;

    void* sp = nullptr;
    cudaGetSymbolAddress(&sp, g_scratch);
    char* S = (char*)sp;
    __half* suph = (__half*)(S + O_SUPH);
    __half* qryh = (__half*)(S + O_QRYH);
    __half* wqh  = (__half*)(S + O_WQH);
    __half* wkh  = (__half*)(S + O_WKH);
    __half* wvh  = (__half*)(S + O_WVH);
    __half* qT   = (__half*)(S + O_QTH);
    __half* kT   = (__half*)(S + O_KTH);
    __half* vN   = (__half*)(S + O_VNH);
    float*  atf  = (float*)(S + O_ATF);
    __half* prh  = (__half*)(S + O_PRH);
    float*  tpf  = (float*)(S + O_TMPF);

    const long long sXh = (long long)FEAT * NPTS;     // 655360 (halfs)
    const long long sAt = (long long)FEAT * FEAT;     // 102400

    static bool attr_set = false;
    if (!attr_set) {
        cudaFuncSetAttribute(qkv_kernel,
                             cudaFuncAttributeMaxDynamicSharedMemorySize, SMEM2_TOTAL_BYTES);
        cudaFuncSetAttribute(gemm_h_kernel<OM_F32A>,
                             cudaFuncAttributeMaxDynamicSharedMemorySize, SMEM_TOTAL_BYTES);
        cudaFuncSetAttribute(gemm_h_kernel<OM_F32RES>,
                             cudaFuncAttributeMaxDynamicSharedMemorySize, SMEM_TOTAL_BYTES);
        attr_set = true;
    }

    const float alpha = 1.0f / sqrtf((float)FEAT);
    const int nX4 = NB * FEAT * NPTS / 4;   // 5242880
    const int nW4 = NPTS * NPTS / 4;        // 1048576

    // fp32 -> fp16 converts (R8-style)
    f2h_kernel<<<nX4 / 256, 256>>>(support, suph, nX4);
    f2h_kernel<<<nX4 / 256, 256>>>(query, qryh, nX4);
    f2h_kernel<<<nW4 / 256, 256>>>(Wq, wqh, nW4);
    f2h_kernel<<<nW4 / 256, 256>>>(Wk, wkh, nW4);
    f2h_kernel<<<nW4 / 256, 256>>>(Wv, wvh, nW4);

    // fused persistent QKV, 256x128 tiles, 1 CTA/SM
    qkv_kernel<<<148, 256, SMEM2_TOTAL_BYTES>>>(qryh, suph, wqh, wkh, wvh, qT, kT, vN);
    // attn logits fp32: M=N=320, K=2048 (128x128 core)
    gemm_h_kernel<OM_F32A><<<288, 128, SMEM_TOTAL_BYTES>>>(
        qT, kT, (char*)atf, nullptr, 320, 320, 2048, 2048, 2048, 320,
        sXh, sXh, sAt, 0, alpha, 288, 3);
    // warp-per-row softmax -> fp16 probs
    softmax_kernel<<<NB * FEAT / 8, 256>>>(atf, prh);
    // AV + residual: M=320, N=2048, K=320 (128x128 core)
    gemm_h_kernel<OM_F32RES><<<296, 128, SMEM_TOTAL_BYTES>>>(
        prh, vN, (char*)tpf, query, 320, 2048, 320, 320, 320, 2048,
        sAt, sXh, sXh, sXh, 1.f, 1536, 16);
    // LayerNorm (R8 exact)
    ln_kernel<<<dim3(NPTS / 256, NB), 256>>>(tpf, gamma, beta, out);
}

// round 12
// speedup vs baseline: 1.0743x; 1.0144x over previous
#include <cuda_runtime.h>
#include <cuda_fp16.h>
#include <cstdint>
#include <cmath>

#define NB 32
#define FEAT 320
#define NPTS 2048

static __device__ float g_scratch[87162880];   // 348 MB

// byte offsets into scratch
#define O_SUPH 0LL
#define O_QRYH 41943040LL
#define O_WQH  83886080LL
#define O_WKH  92274688LL
#define O_WVH  100663296LL
#define O_QTH  109051904LL
#define O_KTH  150994944LL
#define O_VNH  192937984LL
#define O_ATF  234881024LL
#define O_PRH  247988224LL
#define O_TMPF 254541824LL

#define STAGE_BYTES 32768          // A 16KB + B 16KB (fp16, BK=64)
#define SMEM_TOTAL_BYTES (3 * STAGE_BYTES)

#define OM_HALF   0
#define OM_TRANS  1
#define OM_F32A   2
#define OM_F32RES 3

// ---------------- PTX helpers ----------------
__device__ __forceinline__ uint32_t smem_u32(const void* p) {
    uint32_t a;
    asm("{ .reg .u64 t; cvta.to.shared.u64 t, %1; cvt.u32.u64 %0, t; }" : "=r"(a) : "l"(p));
    return a;
}

__device__ __forceinline__ void mma_f16(float* d, const uint32_t* a, const uint32_t* b) {
    asm volatile(
        "mma.sync.aligned.m16n8k16.row.col.f32.f16.f16.f32 "
        "{%0,%1,%2,%3}, {%4,%5,%6,%7}, {%8,%9}, {%0,%1,%2,%3};"
        : "+f"(d[0]), "+f"(d[1]), "+f"(d[2]), "+f"(d[3])
        : "r"(a[0]), "r"(a[1]), "r"(a[2]), "r"(a[3]), "r"(b[0]), "r"(b[1]));
}

__device__ __forceinline__ void ldsm4(uint32_t* r, uint32_t addr) {
    asm volatile("ldmatrix.sync.aligned.m8n8.x4.shared.b16 {%0,%1,%2,%3}, [%4];"
                 : "=r"(r[0]), "=r"(r[1]), "=r"(r[2]), "=r"(r[3]) : "r"(addr));
}

__device__ __forceinline__ void cpasync16(uint32_t dst, const void* src, bool pred) {
    int sz = pred ? 16 : 0;
    asm volatile("cp.async.cg.shared.global [%0], [%1], 16, %2;"
                 :: "r"(dst), "l"(src), "r"(sz) : "memory");
}
#define CP_COMMIT() asm volatile("cp.async.commit_group;" ::: "memory")
#define CP_WAIT1()  asm volatile("cp.async.wait_group 1;" ::: "memory")

// ---------------- fp16 tile core (register-pipelined) — R8 exact ----------------
template<int OM>
__device__ __forceinline__ void run_tile_h(
    const __half* __restrict__ A, const __half* __restrict__ B,
    char* __restrict__ Cb, const float* __restrict__ D,
    int M, int N, int K, int lda, int ldb, int ldc, long long sCb,
    int bm, int bn, float alpha, uint32_t sb, char* smem)
{
    const int tid  = threadIdx.x;
    const int lane = tid & 31;
    const int warp = tid >> 5;
    const int wm = warp & 1;
    const int wn = warp >> 1;

    const int r0  = tid >> 3;          // 0..15
    const int seg = tid & 7;
    const uint32_t xorterm = (uint32_t)((seg ^ (r0 & 7)) << 4);

    const int mrowA = ((lane >> 3) & 1) * 8 + (lane & 7);
    const int khA   = lane >> 4;              // 0/1
    const int nrowB = (lane >> 4) * 8 + (lane & 7);
    const int khB   = (lane >> 3) & 1;
    uint32_t offA[4], phA[4], offB[4], phB[4];
#pragma unroll
    for (int mt = 0; mt < 4; mt++) {
        int rowA = wm * 64 + mt * 16 + mrowA;
        offA[mt] = (uint32_t)(rowA * 128);
        phA[mt]  = (uint32_t)(rowA & 7);
    }
#pragma unroll
    for (int np = 0; np < 4; np++) {
        int rowB = wn * 64 + np * 16 + nrowB;
        offB[np] = (uint32_t)(rowB * 128);
        phB[np]  = (uint32_t)(rowB & 7);
    }

    float acc[4][8][4];
#pragma unroll
    for (int i = 0; i < 4; i++)
#pragma unroll
        for (int j = 0; j < 8; j++)
#pragma unroll
            for (int r = 0; r < 4; r++) acc[i][j][r] = 0.f;

    const int NC = K >> 6;   // BK=64

    auto ISSUE = [&](int c) {
        const int k0 = c << 6;
        const uint32_t aB = sb + (uint32_t)((c % 3) * STAGE_BYTES);
        const uint32_t bB = aB + 16384;
#pragma unroll
        for (int i = 0; i < 8; i++) {
            int r = r0 + 16 * i;
            int gr = bm + r;
            bool p = gr < M;
            cpasync16(aB + (uint32_t)(r * 128) + xorterm,
                      A + (long long)(p ? gr : 0) * lda + k0 + seg * 8, p);
        }
#pragma unroll
        for (int i = 0; i < 8; i++) {
            int r = r0 + 16 * i;
            int gn = bn + r;
            bool p = gn < N;
            cpasync16(bB + (uint32_t)(r * 128) + xorterm,
                      B + (long long)(p ? gn : 0) * ldb + k0 + seg * 8, p);
        }
        CP_COMMIT();
    };

    uint32_t afr[2][4][4];
    uint32_t bfr[2][8][2];

    ISSUE(0);
    ISSUE(1);

    for (int c = 0; c < NC; c++) {
        CP_WAIT1();
        __syncthreads();

        const uint32_t aB = sb + (uint32_t)((c % 3) * STAGE_BYTES);
        const uint32_t bB = aB + 16384;

        {
            const uint32_t s16 = (uint32_t)khA;
#pragma unroll
            for (int mt = 0; mt < 4; mt++)
                ldsm4(afr[0][mt], aB + offA[mt] + ((s16 ^ phA[mt]) << 4));
        }
        {
            const uint32_t s16 = (uint32_t)khB;
#pragma unroll
            for (int np = 0; np < 4; np++) {
                uint32_t r[4];
                ldsm4(r, bB + offB[np] + ((s16 ^ phB[np]) << 4));
                bfr[0][2 * np][0] = r[0];     bfr[0][2 * np][1] = r[1];
                bfr[0][2 * np + 1][0] = r[2]; bfr[0][2 * np + 1][1] = r[3];
            }
        }

        if (c + 2 < NC) ISSUE(c + 2);
        else CP_COMMIT();

#pragma unroll
        for (int ks = 0; ks < 4; ks++) {
            const int cur = ks & 1;
            const int nxt = cur ^ 1;
            if (ks < 3) {
                const uint32_t sA16 = (uint32_t)(2 * (ks + 1) + khA);
#pragma unroll
                for (int mt = 0; mt < 4; mt++)
                    ldsm4(afr[nxt][mt], aB + offA[mt] + ((sA16 ^ phA[mt]) << 4));
                const uint32_t sB16 = (uint32_t)(2 * (ks + 1) + khB);
#pragma unroll
                for (int np = 0; np < 4; np++) {
                    uint32_t r[4];
                    ldsm4(r, bB + offB[np] + ((sB16 ^ phB[np]) << 4));
                    bfr[nxt][2 * np][0] = r[0];     bfr[nxt][2 * np][1] = r[1];
                    bfr[nxt][2 * np + 1][0] = r[2]; bfr[nxt][2 * np + 1][1] = r[3];
                }
            }
#pragma unroll
            for (int mt = 0; mt < 4; mt++)
#pragma unroll
                for (int nt = 0; nt < 8; nt++)
                    mma_f16(acc[mt][nt], afr[cur][mt], bfr[cur][nt]);
        }
    }

    // ---------------- epilogues ----------------
    if (OM == OM_HALF) {
        __half* C = (__half*)Cb;
#pragma unroll
        for (int mt = 0; mt < 4; mt++) {
#pragma unroll
            for (int nt = 0; nt < 8; nt++) {
                int row = bm + wm * 64 + mt * 16 + (lane >> 2);
                int col = bn + wn * 64 + nt * 8 + ((lane & 3) << 1);
                __half2 h0 = __float22half2_rn(make_float2(acc[mt][nt][0], acc[mt][nt][1]));
                __half2 h1 = __float22half2_rn(make_float2(acc[mt][nt][2], acc[mt][nt][3]));
                *reinterpret_cast<__half2*>(C + (long long)row * ldc + col) = h0;
                *reinterpret_cast<__half2*>(C + (long long)(row + 8) * ldc + col) = h1;
            }
        }
    } else if (OM == OM_F32A || OM == OM_F32RES) {
        float* C = (float*)Cb;
#pragma unroll
        for (int mt = 0; mt < 4; mt++) {
#pragma unroll
            for (int nt = 0; nt < 8; nt++) {
                int row = bm + wm * 64 + mt * 16 + (lane >> 2);
                int col = bn + wn * 64 + nt * 8 + ((lane & 3) << 1);
                if (col < N) {
                    if (row < M) {
                        long long i0 = (long long)row * ldc + col;
                        float2 v;
                        v.x = alpha * acc[mt][nt][0];
                        v.y = alpha * acc[mt][nt][1];
                        if (OM == OM_F32RES) { v.x += D[i0]; v.y += D[i0 + 1]; }
                        *reinterpret_cast<float2*>(C + i0) = v;
                    }
                    if (row + 8 < M) {
                        long long i1 = (long long)(row + 8) * ldc + col;
                        float2 v;
                        v.x = alpha * acc[mt][nt][2];
                        v.y = alpha * acc[mt][nt][3];
                        if (OM == OM_F32RES) { v.x += D[i1]; v.y += D[i1 + 1]; }
                        *reinterpret_cast<float2*>(C + i1) = v;
                    }
                }
            }
        }
    } else {   // OM_TRANS: scatter C[b][n][m%FEAT] as fp16 via smem staging
        float* Cs = reinterpret_cast<float*>(smem);
        __half* Ch = (__half*)Cb;
        __syncthreads();
#pragma unroll
        for (int mt = 0; mt < 4; mt++) {
#pragma unroll
            for (int nt = 0; nt < 8; nt++) {
                int nl = wn * 64 + nt * 8 + ((lane & 3) << 1);
                int m0 = wm * 64 + mt * 16 + (lane >> 2);
                Cs[nl * 132 + m0]           = acc[mt][nt][0];
                Cs[(nl + 1) * 132 + m0]     = acc[mt][nt][1];
                Cs[nl * 132 + m0 + 8]       = acc[mt][nt][2];
                Cs[(nl + 1) * 132 + m0 + 8] = acc[mt][nt][3];
            }
        }
        __syncthreads();
#pragma unroll
        for (int it = 0; it < 32; it++) {
            int linear = tid + it * 128;
            int row = linear >> 5;
            int c4  = linear & 31;
            int n_g = bn + row;
            int m_g = bm + c4 * 4;
            int bb  = m_g / FEAT;
            int mm  = m_g - bb * FEAT;
            float4 v = *reinterpret_cast<const float4*>(&Cs[row * 132 + c4 * 4]);
            __half2 h0 = __float22half2_rn(make_float2(v.x, v.y));
            __half2 h1 = __float22half2_rn(make_float2(v.z, v.w));
            __half2* dst = reinterpret_cast<__half2*>(
                Ch + (long long)bb * sCb + (long long)n_g * ldc + mm);
            dst[0] = h0; dst[1] = h1;
        }
    }
}

// ---------------- fused persistent QKV (R8 exact) ----------------
#define QKV_TILES_PER_OP 1280
#define QKV_NTILES 3840

__global__ __launch_bounds__(128, 2)
void qkv_kernel(const __half* __restrict__ qryh, const __half* __restrict__ suph,
                const __half* __restrict__ wq, const __half* __restrict__ wk,
                const __half* __restrict__ wv,
                __half* __restrict__ qT, __half* __restrict__ kT, __half* __restrict__ vN)
{
    extern __shared__ char smem[];
    const uint32_t sb = smem_u32(smem);
    const long long sX = (long long)FEAT * NPTS;

    for (int t = blockIdx.x; t < QKV_NTILES; t += gridDim.x) {
        int op = t / QKV_TILES_PER_OP;
        int r  = t - op * QKV_TILES_PER_OP;
        int bm = (r >> 4) * 128;
        int bn = (r & 15) * 128;
        __syncthreads();
        if (op == 0) {
            run_tile_h<OM_HALF>(suph, wq, (char*)qT, nullptr,
                                NB * FEAT, 2048, 2048, 2048, 2048, 2048, 0,
                                bm, bn, 1.f, sb, smem);
        } else if (op == 1) {
            run_tile_h<OM_HALF>(qryh, wk, (char*)kT, nullptr,
                                NB * FEAT, 2048, 2048, 2048, 2048, 2048, 0,
                                bm, bn, 1.f, sb, smem);
        } else {
            run_tile_h<OM_TRANS>(qryh, wv, (char*)vN, nullptr,
                                 NB * FEAT, 2048, 2048, 2048, 2048, 320, sX,
                                 bm, bn, 1.f, sb, smem);
        }
    }
}

// ---------------- generic persistent batched GEMM (R8 exact) ----------------
template<int OM>
__global__ __launch_bounds__(128, 2)
void gemm_h_kernel(const __half* __restrict__ Ag, const __half* __restrict__ Bg,
                   char* __restrict__ Cg, const float* __restrict__ Dg,
                   int M, int N, int K, int lda, int ldb, int ldc,
                   long long sA, long long sB, long long sC, long long sD,
                   float alpha, int ntiles, int tn)
{
    extern __shared__ char smem[];
    const uint32_t sb = smem_u32(smem);
    const int per = ((M + 127) >> 7) * tn;
    const int esz = (OM == OM_HALF || OM == OM_TRANS) ? 2 : 4;

    for (int t = blockIdx.x; t < ntiles; t += gridDim.x) {
        int b = t / per;
        int r = t - b * per;
        int bm = (r / tn) * 128;
        int bn = (r % tn) * 128;
        __syncthreads();
        run_tile_h<OM>(Ag + (long long)b * sA, Bg + (long long)b * sB,
                       Cg + (long long)b * sC * esz,
                       Dg ? (Dg + (long long)b * sD) : nullptr,
                       M, N, K, lda, ldb, ldc, 0, bm, bn, alpha, sb, smem);
    }
}

// ---------------- convert (R8 exact) ----------------
__global__ __launch_bounds__(256) void f2h_kernel(const float* __restrict__ in,
                                                  __half* __restrict__ out, int n4)
{
    int i = blockIdx.x * 256 + threadIdx.x;
    if (i < n4) {
        float4 v = reinterpret_cast<const float4*>(in)[i];
        __half2 h0 = __float22half2_rn(make_float2(v.x, v.y));
        __half2 h1 = __float22half2_rn(make_float2(v.z, v.w));
        reinterpret_cast<__half2*>(out)[2 * i]     = h0;
        reinterpret_cast<__half2*>(out)[2 * i + 1] = h1;
    }
}

// ---------------- warp-per-row softmax (R10, measured 7.7us) ----------------
__global__ __launch_bounds__(256) void softmax_kernel(const float* __restrict__ attn,
                                                      __half* __restrict__ probs)
{
    const int lane = threadIdx.x & 31;
    const int wrow = (blockIdx.x << 3) + (threadIdx.x >> 5);
    const float* row = attn + (long long)wrow * FEAT;

    float v[10];
    float m = -1e30f;
#pragma unroll
    for (int j = 0; j < 10; j++) {
        v[j] = row[lane + 32 * j];
        m = fmaxf(m, v[j]);
    }
#pragma unroll
    for (int s = 16; s > 0; s >>= 1)
        m = fmaxf(m, __shfl_xor_sync(0xffffffff, m, s));
    float sum = 0.f;
#pragma unroll
    for (int j = 0; j < 10; j++) {
        v[j] = expf(v[j] - m);
        sum += v[j];
    }
#pragma unroll
    for (int s = 16; s > 0; s >>= 1)
        sum += __shfl_xor_sync(0xffffffff, sum, s);
    float inv = 1.f / sum;
    __half* orow = probs + (long long)wrow * FEAT;
#pragma unroll
    for (int j = 0; j < 10; j++)
        orow[lane + 32 * j] = __float2half(v[j] * inv);
}

// ---------------- LayerNorm (R8 exact) ----------------
__global__ __launch_bounds__(256) void ln_kernel(const float* __restrict__ tp,
                                                 const float* __restrict__ gamma,
                                                 const float* __restrict__ beta,
                                                 float* __restrict__ out)
{
    const int b = blockIdx.y;
    const int o = blockIdx.x * 256 + threadIdx.x;
    const float* base = tp + (long long)b * (FEAT * NPTS) + o;
    float s = 0.f, s2 = 0.f;
#pragma unroll 4
    for (int l = 0; l < FEAT; l++) {
        float v = base[(long long)l * NPTS];
        s += v;
        s2 += v * v;
    }
    const float inv = 1.f / FEAT;
    float mu = s * inv;
    float var = s2 * inv - mu * mu;
    float rstd = rsqrtf(var + 1e-5f);
    float* ob = out + (long long)b * (FEAT * NPTS) + o;
#pragma unroll 4
    for (int l = 0; l < FEAT; l++) {
        float v = base[(long long)l * NPTS];
        ob[(long long)l * NPTS] = (v - mu) * rstd * gamma[l] + beta[l];
    }
}

// ---------------- launch ----------------
extern "C" void kernel_launch(void* const* d_in, const int* in_sizes, int n_in,
                              void* d_out, int out_size)
{
    const float* query   = (const float*)d_in[0];
    const float* support = (const float*)d_in[1];
    const float* Wq      = (const float*)d_in[2];
    const float* Wk      = (const float*)d_in[3];
    const float* Wv      = (const float*)d_in[4];
    const float* gamma   = (const float*)d_in[5];
    const float* beta    = (const float*)d_in[6];
    float* out = (float*)d_out;

    void* sp = nullptr;
    cudaGetSymbolAddress(&sp, g_scratch);
    char* S = (char*)sp;
    __half* suph = (__half*)(S + O_SUPH);
    __half* qryh = (__half*)(S + O_QRYH);
    __half* wqh  = (__half*)(S + O_WQH);
    __half* wkh  = (__half*)(S + O_WKH);
    __half* wvh  = (__half*)(S + O_WVH);
    __half* qT   = (__half*)(S + O_QTH);
    __half* kT   = (__half*)(S + O_KTH);
    __half* vN   = (__half*)(S + O_VNH);
    float*  atf  = (float*)(S + O_ATF);
    __half* prh  = (__half*)(S + O_PRH);
    float*  tpf  = (float*)(S + O_TMPF);

    const long long sXh = (long long)FEAT * NPTS;     // 655360 (halfs)
    const long long sAt = (long long)FEAT * FEAT;     // 102400

    static bool attr_set = false;
    if (!attr_set) {
        cudaFuncSetAttribute(qkv_kernel,
                             cudaFuncAttributeMaxDynamicSharedMemorySize, SMEM_TOTAL_BYTES);
        cudaFuncSetAttribute(gemm_h_kernel<OM_F32A>,
                             cudaFuncAttributeMaxDynamicSharedMemorySize, SMEM_TOTAL_BYTES);
        cudaFuncSetAttribute(gemm_h_kernel<OM_F32RES>,
                             cudaFuncAttributeMaxDynamicSharedMemorySize, SMEM_TOTAL_BYTES);
        attr_set = true;
    }

    const size_t smb = SMEM_TOTAL_BYTES;
    const float alpha = 1.0f / sqrtf((float)FEAT);
    const int nX4 = NB * FEAT * NPTS / 4;   // 5242880
    const int nW4 = NPTS * NPTS / 4;        // 1048576

    // fp32 -> fp16 conversions (R8 exact)
    f2h_kernel<<<nX4 / 256, 256>>>(support, suph, nX4);
    f2h_kernel<<<nX4 / 256, 256>>>(query, qryh, nX4);
    f2h_kernel<<<nW4 / 256, 256>>>(Wq, wqh, nW4);
    f2h_kernel<<<nW4 / 256, 256>>>(Wk, wkh, nW4);
    f2h_kernel<<<nW4 / 256, 256>>>(Wv, wvh, nW4);

    // fused persistent QKV (R8 exact: 128x128 tiles, 2 CTAs/SM)
    qkv_kernel<<<296, 128, smb>>>(qryh, suph, wqh, wkh, wvh, qT, kT, vN);
    // attn logits fp32: M=N=320, K=2048
    gemm_h_kernel<OM_F32A><<<288, 128, smb>>>(
        qT, kT, (char*)atf, nullptr, 320, 320, 2048, 2048, 2048, 320,
        sXh, sXh, sAt, 0, alpha, 288, 3);
    // warp-per-row softmax -> fp16 probs
    softmax_kernel<<<NB * FEAT / 8, 256>>>(atf, prh);
    // AV + residual: M=320, N=2048, K=320
    gemm_h_kernel<OM_F32RES><<<296, 128, smb>>>(
        prh, vN, (char*)tpf, query, 320, 2048, 320, 320, 320, 2048,
        sAt, sXh, sXh, sXh, 1.f, 1536, 16);
    // LayerNorm (R8 exact)
    ln_kernel<<<dim3(NPTS / 256, NB), 256>>>(tpf, gamma, beta, out);
}

// round 13
// speedup vs baseline: 1.0986x; 1.0226x over previous
#include <cuda_runtime.h>
#include <cuda_fp16.h>
#include <cstdint>
#include <cmath>

#define NB 32
#define FEAT 320
#define NPTS 2048

static __device__ float g_scratch[87162880];   // 348 MB

// byte offsets into scratch
#define O_SUPH 0LL
#define O_QRYH 41943040LL
#define O_WQH  83886080LL
#define O_WKH  92274688LL
#define O_WVH  100663296LL
#define O_QTH  109051904LL
#define O_KTH  150994944LL
#define O_VNH  192937984LL
#define O_ATF  234881024LL
#define O_PRH  247988224LL
#define O_TMPF 254541824LL

#define STAGE_BYTES 32768          // A 16KB + B 16KB (fp16, BK=64)
#define SMEM_TOTAL_BYTES (3 * STAGE_BYTES)

#define OM_HALF   0
#define OM_TRANS  1
#define OM_F32A   2
#define OM_F32RES 3

// ---------------- PTX helpers ----------------
__device__ __forceinline__ uint32_t smem_u32(const void* p) {
    uint32_t a;
    asm("{ .reg .u64 t; cvta.to.shared.u64 t, %1; cvt.u32.u64 %0, t; }" : "=r"(a) : "l"(p));
    return a;
}

__device__ __forceinline__ void mma_f16(float* d, const uint32_t* a, const uint32_t* b) {
    asm volatile(
        "mma.sync.aligned.m16n8k16.row.col.f32.f16.f16.f32 "
        "{%0,%1,%2,%3}, {%4,%5,%6,%7}, {%8,%9}, {%0,%1,%2,%3};"
        : "+f"(d[0]), "+f"(d[1]), "+f"(d[2]), "+f"(d[3])
        : "r"(a[0]), "r"(a[1]), "r"(a[2]), "r"(a[3]), "r"(b[0]), "r"(b[1]));
}

__device__ __forceinline__ void ldsm4(uint32_t* r, uint32_t addr) {
    asm volatile("ldmatrix.sync.aligned.m8n8.x4.shared.b16 {%0,%1,%2,%3}, [%4];"
                 : "=r"(r[0]), "=r"(r[1]), "=r"(r[2]), "=r"(r[3]) : "r"(addr));
}

__device__ __forceinline__ void cpasync16(uint32_t dst, const void* src, bool pred) {
    int sz = pred ? 16 : 0;
    asm volatile("cp.async.cg.shared.global [%0], [%1], 16, %2;"
                 :: "r"(dst), "l"(src), "r"(sz) : "memory");
}
#define CP_COMMIT() asm volatile("cp.async.commit_group;" ::: "memory")
#define CP_WAIT1()  asm volatile("cp.async.wait_group 1;" ::: "memory")

// ---------------- fp16 tile core (register-pipelined) — R8 exact ----------------
template<int OM>
__device__ __forceinline__ void run_tile_h(
    const __half* __restrict__ A, const __half* __restrict__ B,
    char* __restrict__ Cb, const float* __restrict__ D,
    int M, int N, int K, int lda, int ldb, int ldc, long long sCb,
    int bm, int bn, float alpha, uint32_t sb, char* smem)
{
    const int tid  = threadIdx.x;
    const int lane = tid & 31;
    const int warp = tid >> 5;
    const int wm = warp & 1;
    const int wn = warp >> 1;

    const int r0  = tid >> 3;          // 0..15
    const int seg = tid & 7;
    const uint32_t xorterm = (uint32_t)((seg ^ (r0 & 7)) << 4);

    const int mrowA = ((lane >> 3) & 1) * 8 + (lane & 7);
    const int khA   = lane >> 4;              // 0/1
    const int nrowB = (lane >> 4) * 8 + (lane & 7);
    const int khB   = (lane >> 3) & 1;
    uint32_t offA[4], phA[4], offB[4], phB[4];
#pragma unroll
    for (int mt = 0; mt < 4; mt++) {
        int rowA = wm * 64 + mt * 16 + mrowA;
        offA[mt] = (uint32_t)(rowA * 128);
        phA[mt]  = (uint32_t)(rowA & 7);
    }
#pragma unroll
    for (int np = 0; np < 4; np++) {
        int rowB = wn * 64 + np * 16 + nrowB;
        offB[np] = (uint32_t)(rowB * 128);
        phB[np]  = (uint32_t)(rowB & 7);
    }

    float acc[4][8][4];
#pragma unroll
    for (int i = 0; i < 4; i++)
#pragma unroll
        for (int j = 0; j < 8; j++)
#pragma unroll
            for (int r = 0; r < 4; r++) acc[i][j][r] = 0.f;

    const int NC = K >> 6;   // BK=64

    auto ISSUE = [&](int c) {
        const int k0 = c << 6;
        const uint32_t aB = sb + (uint32_t)((c % 3) * STAGE_BYTES);
        const uint32_t bB = aB + 16384;
#pragma unroll
        for (int i = 0; i < 8; i++) {
            int r = r0 + 16 * i;
            int gr = bm + r;
            bool p = gr < M;
            cpasync16(aB + (uint32_t)(r * 128) + xorterm,
                      A + (long long)(p ? gr : 0) * lda + k0 + seg * 8, p);
        }
#pragma unroll
        for (int i = 0; i < 8; i++) {
            int r = r0 + 16 * i;
            int gn = bn + r;
            bool p = gn < N;
            cpasync16(bB + (uint32_t)(r * 128) + xorterm,
                      B + (long long)(p ? gn : 0) * ldb + k0 + seg * 8, p);
        }
        CP_COMMIT();
    };

    uint32_t afr[2][4][4];
    uint32_t bfr[2][8][2];

    ISSUE(0);
    ISSUE(1);

    for (int c = 0; c < NC; c++) {
        CP_WAIT1();
        __syncthreads();

        const uint32_t aB = sb + (uint32_t)((c % 3) * STAGE_BYTES);
        const uint32_t bB = aB + 16384;

        {
            const uint32_t s16 = (uint32_t)khA;
#pragma unroll
            for (int mt = 0; mt < 4; mt++)
                ldsm4(afr[0][mt], aB + offA[mt] + ((s16 ^ phA[mt]) << 4));
        }
        {
            const uint32_t s16 = (uint32_t)khB;
#pragma unroll
            for (int np = 0; np < 4; np++) {
                uint32_t r[4];
                ldsm4(r, bB + offB[np] + ((s16 ^ phB[np]) << 4));
                bfr[0][2 * np][0] = r[0];     bfr[0][2 * np][1] = r[1];
                bfr[0][2 * np + 1][0] = r[2]; bfr[0][2 * np + 1][1] = r[3];
            }
        }

        if (c + 2 < NC) ISSUE(c + 2);
        else CP_COMMIT();

#pragma unroll
        for (int ks = 0; ks < 4; ks++) {
            const int cur = ks & 1;
            const int nxt = cur ^ 1;
            if (ks < 3) {
                const uint32_t sA16 = (uint32_t)(2 * (ks + 1) + khA);
#pragma unroll
                for (int mt = 0; mt < 4; mt++)
                    ldsm4(afr[nxt][mt], aB + offA[mt] + ((sA16 ^ phA[mt]) << 4));
                const uint32_t sB16 = (uint32_t)(2 * (ks + 1) + khB);
#pragma unroll
                for (int np = 0; np < 4; np++) {
                    uint32_t r[4];
                    ldsm4(r, bB + offB[np] + ((sB16 ^ phB[np]) << 4));
                    bfr[nxt][2 * np][0] = r[0];     bfr[nxt][2 * np][1] = r[1];
                    bfr[nxt][2 * np + 1][0] = r[2]; bfr[nxt][2 * np + 1][1] = r[3];
                }
            }
#pragma unroll
            for (int mt = 0; mt < 4; mt++)
#pragma unroll
                for (int nt = 0; nt < 8; nt++)
                    mma_f16(acc[mt][nt], afr[cur][mt], bfr[cur][nt]);
        }
    }

    // ---------------- epilogues ----------------
    if (OM == OM_HALF) {
        __half* C = (__half*)Cb;
#pragma unroll
        for (int mt = 0; mt < 4; mt++) {
#pragma unroll
            for (int nt = 0; nt < 8; nt++) {
                int row = bm + wm * 64 + mt * 16 + (lane >> 2);
                int col = bn + wn * 64 + nt * 8 + ((lane & 3) << 1);
                __half2 h0 = __float22half2_rn(make_float2(acc[mt][nt][0], acc[mt][nt][1]));
                __half2 h1 = __float22half2_rn(make_float2(acc[mt][nt][2], acc[mt][nt][3]));
                *reinterpret_cast<__half2*>(C + (long long)row * ldc + col) = h0;
                *reinterpret_cast<__half2*>(C + (long long)(row + 8) * ldc + col) = h1;
            }
        }
    } else if (OM == OM_F32A || OM == OM_F32RES) {
        float* C = (float*)Cb;
#pragma unroll
        for (int mt = 0; mt < 4; mt++) {
#pragma unroll
            for (int nt = 0; nt < 8; nt++) {
                int row = bm + wm * 64 + mt * 16 + (lane >> 2);
                int col = bn + wn * 64 + nt * 8 + ((lane & 3) << 1);
                if (col < N) {
                    if (row < M) {
                        long long i0 = (long long)row * ldc + col;
                        float2 v;
                        v.x = alpha * acc[mt][nt][0];
                        v.y = alpha * acc[mt][nt][1];
                        if (OM == OM_F32RES) { v.x += D[i0]; v.y += D[i0 + 1]; }
                        *reinterpret_cast<float2*>(C + i0) = v;
                    }
                    if (row + 8 < M) {
                        long long i1 = (long long)(row + 8) * ldc + col;
                        float2 v;
                        v.x = alpha * acc[mt][nt][2];
                        v.y = alpha * acc[mt][nt][3];
                        if (OM == OM_F32RES) { v.x += D[i1]; v.y += D[i1 + 1]; }
                        *reinterpret_cast<float2*>(C + i1) = v;
                    }
                }
            }
        }
    } else {   // OM_TRANS: scatter C[b][n][m%FEAT] as fp16 via smem staging
        float* Cs = reinterpret_cast<float*>(smem);
        __half* Ch = (__half*)Cb;
        __syncthreads();
#pragma unroll
        for (int mt = 0; mt < 4; mt++) {
#pragma unroll
            for (int nt = 0; nt < 8; nt++) {
                int nl = wn * 64 + nt * 8 + ((lane & 3) << 1);
                int m0 = wm * 64 + mt * 16 + (lane >> 2);
                Cs[nl * 132 + m0]           = acc[mt][nt][0];
                Cs[(nl + 1) * 132 + m0]     = acc[mt][nt][1];
                Cs[nl * 132 + m0 + 8]       = acc[mt][nt][2];
                Cs[(nl + 1) * 132 + m0 + 8] = acc[mt][nt][3];
            }
        }
        __syncthreads();
#pragma unroll
        for (int it = 0; it < 32; it++) {
            int linear = tid + it * 128;
            int row = linear >> 5;
            int c4  = linear & 31;
            int n_g = bn + row;
            int m_g = bm + c4 * 4;
            int bb  = m_g / FEAT;
            int mm  = m_g - bb * FEAT;
            float4 v = *reinterpret_cast<const float4*>(&Cs[row * 132 + c4 * 4]);
            __half2 h0 = __float22half2_rn(make_float2(v.x, v.y));
            __half2 h1 = __float22half2_rn(make_float2(v.z, v.w));
            __half2* dst = reinterpret_cast<__half2*>(
                Ch + (long long)bb * sCb + (long long)n_g * ldc + mm);
            dst[0] = h0; dst[1] = h1;
        }
    }
}

// ---------------- fused persistent QKV (R8 exact) ----------------
#define QKV_TILES_PER_OP 1280
#define QKV_NTILES 3840

__global__ __launch_bounds__(128, 2)
void qkv_kernel(const __half* __restrict__ qryh, const __half* __restrict__ suph,
                const __half* __restrict__ wq, const __half* __restrict__ wk,
                const __half* __restrict__ wv,
                __half* __restrict__ qT, __half* __restrict__ kT, __half* __restrict__ vN)
{
    extern __shared__ char smem[];
    const uint32_t sb = smem_u32(smem);
    const long long sX = (long long)FEAT * NPTS;

    for (int t = blockIdx.x; t < QKV_NTILES; t += gridDim.x) {
        int op = t / QKV_TILES_PER_OP;
        int r  = t - op * QKV_TILES_PER_OP;
        int bm = (r >> 4) * 128;
        int bn = (r & 15) * 128;
        __syncthreads();
        if (op == 0) {
            run_tile_h<OM_HALF>(suph, wq, (char*)qT, nullptr,
                                NB * FEAT, 2048, 2048, 2048, 2048, 2048, 0,
                                bm, bn, 1.f, sb, smem);
        } else if (op == 1) {
            run_tile_h<OM_HALF>(qryh, wk, (char*)kT, nullptr,
                                NB * FEAT, 2048, 2048, 2048, 2048, 2048, 0,
                                bm, bn, 1.f, sb, smem);
        } else {
            run_tile_h<OM_TRANS>(qryh, wv, (char*)vN, nullptr,
                                 NB * FEAT, 2048, 2048, 2048, 2048, 320, sX,
                                 bm, bn, 1.f, sb, smem);
        }
    }
}

// ---------------- generic persistent batched GEMM (R8 exact) ----------------
template<int OM>
__global__ __launch_bounds__(128, 2)
void gemm_h_kernel(const __half* __restrict__ Ag, const __half* __restrict__ Bg,
                   char* __restrict__ Cg, const float* __restrict__ Dg,
                   int M, int N, int K, int lda, int ldb, int ldc,
                   long long sA, long long sB, long long sC, long long sD,
                   float alpha, int ntiles, int tn)
{
    extern __shared__ char smem[];
    const uint32_t sb = smem_u32(smem);
    const int per = ((M + 127) >> 7) * tn;
    const int esz = (OM == OM_HALF || OM == OM_TRANS) ? 2 : 4;

    for (int t = blockIdx.x; t < ntiles; t += gridDim.x) {
        int b = t / per;
        int r = t - b * per;
        int bm = (r / tn) * 128;
        int bn = (r % tn) * 128;
        __syncthreads();
        run_tile_h<OM>(Ag + (long long)b * sA, Bg + (long long)b * sB,
                       Cg + (long long)b * sC * esz,
                       Dg ? (Dg + (long long)b * sD) : nullptr,
                       M, N, K, lda, ldb, ldc, 0, bm, bn, alpha, sb, smem);
    }
}

// ---------------- fused convert: 1 launch, STG.128, MLP=2 ----------------
// Pair-indexed (1 pair = 2 float4 in = 1 uint4 out). Each thread reads two
// ADJACENT float4 (32B per lane, line-sharing across the pair of loads) and
// writes one coalesced uint4. Region boundaries (pair units) are multiples
// of 256, so region decode is uniform per block.
#define CP_B0 2621440LL   // support pairs
#define CP_B1 5242880LL   // + query
#define CP_B2 5767168LL   // + Wq
#define CP_B3 6291456LL   // + Wk
#define CP_B4 6815744LL   // + Wv

__device__ __forceinline__ uint32_t pack_h2(float x, float y) {
    __half2 h = __float22half2_rn(make_float2(x, y));
    return *reinterpret_cast<uint32_t*>(&h);
}

__global__ __launch_bounds__(256) void cvt_all_kernel(
    const float* __restrict__ s,  const float* __restrict__ q,
    const float* __restrict__ w0, const float* __restrict__ w1, const float* __restrict__ w2,
    __half* __restrict__ sh, __half* __restrict__ qh,
    __half* __restrict__ h0, __half* __restrict__ h1, __half* __restrict__ h2)
{
    long long blk = (long long)blockIdx.x * 256;
    const float* src; __half* dst; long long off;
    if (blk < CP_B0)      { src = s;  dst = sh; off = blk; }
    else if (blk < CP_B1) { src = q;  dst = qh; off = blk - CP_B0; }
    else if (blk < CP_B2) { src = w0; dst = h0; off = blk - CP_B1; }
    else if (blk < CP_B3) { src = w1; dst = h1; off = blk - CP_B2; }
    else                  { src = w2; dst = h2; off = blk - CP_B3; }
    off += threadIdx.x;
    const float4* s4 = reinterpret_cast<const float4*>(src);
    float4 a = s4[2 * off];
    float4 b = s4[2 * off + 1];
    uint4 u;
    u.x = pack_h2(a.x, a.y);
    u.y = pack_h2(a.z, a.w);
    u.z = pack_h2(b.x, b.y);
    u.w = pack_h2(b.z, b.w);
    reinterpret_cast<uint4*>(dst)[off] = u;
}

// ---------------- warp-per-row softmax (R10, measured 7.7us) ----------------
__global__ __launch_bounds__(256) void softmax_kernel(const float* __restrict__ attn,
                                                      __half* __restrict__ probs)
{
    const int lane = threadIdx.x & 31;
    const int wrow = (blockIdx.x << 3) + (threadIdx.x >> 5);
    const float* row = attn + (long long)wrow * FEAT;

    float v[10];
    float m = -1e30f;
#pragma unroll
    for (int j = 0; j < 10; j++) {
        v[j] = row[lane + 32 * j];
        m = fmaxf(m, v[j]);
    }
#pragma unroll
    for (int s = 16; s > 0; s >>= 1)
        m = fmaxf(m, __shfl_xor_sync(0xffffffff, m, s));
    float sum = 0.f;
#pragma unroll
    for (int j = 0; j < 10; j++) {
        v[j] = expf(v[j] - m);
        sum += v[j];
    }
#pragma unroll
    for (int s = 16; s > 0; s >>= 1)
        sum += __shfl_xor_sync(0xffffffff, sum, s);
    float inv = 1.f / sum;
    __half* orow = probs + (long long)wrow * FEAT;
#pragma unroll
    for (int j = 0; j < 10; j++)
        orow[lane + 32 * j] = __float2half(v[j] * inv);
}

// ---------------- LayerNorm (R8 exact) ----------------
__global__ __launch_bounds__(256) void ln_kernel(const float* __restrict__ tp,
                                                 const float* __restrict__ gamma,
                                                 const float* __restrict__ beta,
                                                 float* __restrict__ out)
{
    const int b = blockIdx.y;
    const int o = blockIdx.x * 256 + threadIdx.x;
    const float* base = tp + (long long)b * (FEAT * NPTS) + o;
    float s = 0.f, s2 = 0.f;
#pragma unroll 4
    for (int l = 0; l < FEAT; l++) {
        float v = base[(long long)l * NPTS];
        s += v;
        s2 += v * v;
    }
    const float inv = 1.f / FEAT;
    float mu = s * inv;
    float var = s2 * inv - mu * mu;
    float rstd = rsqrtf(var + 1e-5f);
    float* ob = out + (long long)b * (FEAT * NPTS) + o;
#pragma unroll 4
    for (int l = 0; l < FEAT; l++) {
        float v = base[(long long)l * NPTS];
        ob[(long long)l * NPTS] = (v - mu) * rstd * gamma[l] + beta[l];
    }
}

// ---------------- launch ----------------
extern "C" void kernel_launch(void* const* d_in, const int* in_sizes, int n_in,
                              void* d_out, int out_size)
{
    const float* query   = (const float*)d_in[0];
    const float* support = (const float*)d_in[1];
    const float* Wq      = (const float*)d_in[2];
    const float* Wk      = (const float*)d_in[3];
    const float* Wv      = (const float*)d_in[4];
    const float* gamma   = (const float*)d_in[5];
    const float* beta    = (const float*)d_in[6];
    float* out = (float*)d_out;

    void* sp = nullptr;
    cudaGetSymbolAddress(&sp, g_scratch);
    char* S = (char*)sp;
    __half* suph = (__half*)(S + O_SUPH);
    __half* qryh = (__half*)(S + O_QRYH);
    __half* wqh  = (__half*)(S + O_WQH);
    __half* wkh  = (__half*)(S + O_WKH);
    __half* wvh  = (__half*)(S + O_WVH);
    __half* qT   = (__half*)(S + O_QTH);
    __half* kT   = (__half*)(S + O_KTH);
    __half* vN   = (__half*)(S + O_VNH);
    float*  atf  = (float*)(S + O_ATF);
    __half* prh  = (__half*)(S + O_PRH);
    float*  tpf  = (float*)(S + O_TMPF);

    const long long sXh = (long long)FEAT * NPTS;     // 655360 (halfs)
    const long long sAt = (long long)FEAT * FEAT;     // 102400

    static bool attr_set = false;
    if (!attr_set) {
        cudaFuncSetAttribute(qkv_kernel,
                             cudaFuncAttributeMaxDynamicSharedMemorySize, SMEM_TOTAL_BYTES);
        cudaFuncSetAttribute(gemm_h_kernel<OM_F32A>,
                             cudaFuncAttributeMaxDynamicSharedMemorySize, SMEM_TOTAL_BYTES);
        cudaFuncSetAttribute(gemm_h_kernel<OM_F32RES>,
                             cudaFuncAttributeMaxDynamicSharedMemorySize, SMEM_TOTAL_BYTES);
        attr_set = true;
    }

    const size_t smb = SMEM_TOTAL_BYTES;
    const float alpha = 1.0f / sqrtf((float)FEAT);

    // single fused fp32->fp16 convert (support, query, Wq, Wk, Wv)
    cvt_all_kernel<<<(int)(CP_B4 / 256), 256>>>(
        support, query, Wq, Wk, Wv, suph, qryh, wqh, wkh, wvh);

    // fused persistent QKV (R8 exact: 128x128 tiles, 2 CTAs/SM)
    qkv_kernel<<<296, 128, smb>>>(qryh, suph, wqh, wkh, wvh, qT, kT, vN);
    // attn logits fp32: M=N=320, K=2048
    gemm_h_kernel<OM_F32A><<<288, 128, smb>>>(
        qT, kT, (char*)atf, nullptr, 320, 320, 2048, 2048, 2048, 320,
        sXh, sXh, sAt, 0, alpha, 288, 3);
    // warp-per-row softmax -> fp16 probs
    softmax_kernel<<<NB * FEAT / 8, 256>>>(atf, prh);
    // AV + residual: M=320, N=2048, K=320
    gemm_h_kernel<OM_F32RES><<<296, 128, smb>>>(
        prh, vN, (char*)tpf, query, 320, 2048, 320, 320, 320, 2048,
        sAt, sXh, sXh, sXh, 1.f, 1536, 16);
    // LayerNorm (R8 exact)
    ln_kernel<<<dim3(NPTS / 256, NB), 256>>>(tpf, gamma, beta, out);
}

// round 15
// speedup vs baseline: 1.1111x; 1.0114x over previous
#include <cuda_runtime.h>
#include <cuda_fp16.h>
#include <cstdint>
#include <cmath>

#define NB 32
#define FEAT 320
#define NPTS 2048

static __device__ float g_scratch[87162880];   // 348 MB

// byte offsets into scratch
#define O_SUPH 0LL
#define O_QRYH 41943040LL
#define O_WQH  83886080LL
#define O_WKH  92274688LL
#define O_WVH  100663296LL
#define O_QTH  109051904LL
#define O_KTH  150994944LL
#define O_VNH  192937984LL
#define O_ATF  234881024LL
#define O_PRH  247988224LL
#define O_TMPH 254541824LL

#define STAGE_BYTES 32768          // A 16KB + B 16KB (fp16, BK=64)
#define SMEM_TOTAL_BYTES (3 * STAGE_BYTES)

#define OM_HALF   0
#define OM_TRANS  1
#define OM_F32A   2
#define OM_HRES   3   // +fp32 residual D, store fp16

// ---------------- PTX helpers ----------------
__device__ __forceinline__ uint32_t smem_u32(const void* p) {
    uint32_t a;
    asm("{ .reg .u64 t; cvta.to.shared.u64 t, %1; cvt.u32.u64 %0, t; }" : "=r"(a) : "l"(p));
    return a;
}

__device__ __forceinline__ void mma_f16(float* d, const uint32_t* a, const uint32_t* b) {
    asm volatile(
        "mma.sync.aligned.m16n8k16.row.col.f32.f16.f16.f32 "
        "{%0,%1,%2,%3}, {%4,%5,%6,%7}, {%8,%9}, {%0,%1,%2,%3};"
        : "+f"(d[0]), "+f"(d[1]), "+f"(d[2]), "+f"(d[3])
        : "r"(a[0]), "r"(a[1]), "r"(a[2]), "r"(a[3]), "r"(b[0]), "r"(b[1]));
}

__device__ __forceinline__ void ldsm4(uint32_t* r, uint32_t addr) {
    asm volatile("ldmatrix.sync.aligned.m8n8.x4.shared.b16 {%0,%1,%2,%3}, [%4];"
                 : "=r"(r[0]), "=r"(r[1]), "=r"(r[2]), "=r"(r[3]) : "r"(addr));
}

__device__ __forceinline__ void cpasync16(uint32_t dst, const void* src, bool pred) {
    int sz = pred ? 16 : 0;
    asm volatile("cp.async.cg.shared.global [%0], [%1], 16, %2;"
                 :: "r"(dst), "l"(src), "r"(sz) : "memory");
}
#define CP_COMMIT() asm volatile("cp.async.commit_group;" ::: "memory")
#define CP_WAIT1()  asm volatile("cp.async.wait_group 1;" ::: "memory")

// ---------------- fp16 tile core (register-pipelined) — R8-proven ----------------
template<int OM>
__device__ __forceinline__ void run_tile_h(
    const __half* __restrict__ A, const __half* __restrict__ B,
    char* __restrict__ Cb, const float* __restrict__ D,
    int M, int N, int K, int lda, int ldb, int ldc, long long sCb,
    int bm, int bn, float alpha, uint32_t sb, char* smem)
{
    const int tid  = threadIdx.x;
    const int lane = tid & 31;
    const int warp = tid >> 5;
    const int wm = warp & 1;
    const int wn = warp >> 1;

    const int r0  = tid >> 3;          // 0..15
    const int seg = tid & 7;
    const uint32_t xorterm = (uint32_t)((seg ^ (r0 & 7)) << 4);

    const int mrowA = ((lane >> 3) & 1) * 8 + (lane & 7);
    const int khA   = lane >> 4;              // 0/1
    const int nrowB = (lane >> 4) * 8 + (lane & 7);
    const int khB   = (lane >> 3) & 1;
    uint32_t offA[4], phA[4], offB[4], phB[4];
#pragma unroll
    for (int mt = 0; mt < 4; mt++) {
        int rowA = wm * 64 + mt * 16 + mrowA;
        offA[mt] = (uint32_t)(rowA * 128);
        phA[mt]  = (uint32_t)(rowA & 7);
    }
#pragma unroll
    for (int np = 0; np < 4; np++) {
        int rowB = wn * 64 + np * 16 + nrowB;
        offB[np] = (uint32_t)(rowB * 128);
        phB[np]  = (uint32_t)(rowB & 7);
    }

    float acc[4][8][4];
#pragma unroll
    for (int i = 0; i < 4; i++)
#pragma unroll
        for (int j = 0; j < 8; j++)
#pragma unroll
            for (int r = 0; r < 4; r++) acc[i][j][r] = 0.f;

    const int NC = K >> 6;   // BK=64

    auto ISSUE = [&](int c) {
        const int k0 = c << 6;
        const uint32_t aB = sb + (uint32_t)((c % 3) * STAGE_BYTES);
        const uint32_t bB = aB + 16384;
#pragma unroll
        for (int i = 0; i < 8; i++) {
            int r = r0 + 16 * i;
            int gr = bm + r;
            bool p = gr < M;
            cpasync16(aB + (uint32_t)(r * 128) + xorterm,
                      A + (long long)(p ? gr : 0) * lda + k0 + seg * 8, p);
        }
#pragma unroll
        for (int i = 0; i < 8; i++) {
            int r = r0 + 16 * i;
            int gn = bn + r;
            bool p = gn < N;
            cpasync16(bB + (uint32_t)(r * 128) + xorterm,
                      B + (long long)(p ? gn : 0) * ldb + k0 + seg * 8, p);
        }
        CP_COMMIT();
    };

    uint32_t afr[2][4][4];
    uint32_t bfr[2][8][2];

    ISSUE(0);
    ISSUE(1);

    for (int c = 0; c < NC; c++) {
        CP_WAIT1();
        __syncthreads();

        const uint32_t aB = sb + (uint32_t)((c % 3) * STAGE_BYTES);
        const uint32_t bB = aB + 16384;

        {
            const uint32_t s16 = (uint32_t)khA;
#pragma unroll
            for (int mt = 0; mt < 4; mt++)
                ldsm4(afr[0][mt], aB + offA[mt] + ((s16 ^ phA[mt]) << 4));
        }
        {
            const uint32_t s16 = (uint32_t)khB;
#pragma unroll
            for (int np = 0; np < 4; np++) {
                uint32_t r[4];
                ldsm4(r, bB + offB[np] + ((s16 ^ phB[np]) << 4));
                bfr[0][2 * np][0] = r[0];     bfr[0][2 * np][1] = r[1];
                bfr[0][2 * np + 1][0] = r[2]; bfr[0][2 * np + 1][1] = r[3];
            }
        }

        if (c + 2 < NC) ISSUE(c + 2);
        else CP_COMMIT();

#pragma unroll
        for (int ks = 0; ks < 4; ks++) {
            const int cur = ks & 1;
            const int nxt = cur ^ 1;
            if (ks < 3) {
                const uint32_t sA16 = (uint32_t)(2 * (ks + 1) + khA);
#pragma unroll
                for (int mt = 0; mt < 4; mt++)
                    ldsm4(afr[nxt][mt], aB + offA[mt] + ((sA16 ^ phA[mt]) << 4));
                const uint32_t sB16 = (uint32_t)(2 * (ks + 1) + khB);
#pragma unroll
                for (int np = 0; np < 4; np++) {
                    uint32_t r[4];
                    ldsm4(r, bB + offB[np] + ((sB16 ^ phB[np]) << 4));
                    bfr[nxt][2 * np][0] = r[0];     bfr[nxt][2 * np][1] = r[1];
                    bfr[nxt][2 * np + 1][0] = r[2]; bfr[nxt][2 * np + 1][1] = r[3];
                }
            }
#pragma unroll
            for (int mt = 0; mt < 4; mt++)
#pragma unroll
                for (int nt = 0; nt < 8; nt++)
                    mma_f16(acc[mt][nt], afr[cur][mt], bfr[cur][nt]);
        }
    }

    // ---------------- epilogues ----------------
    if (OM == OM_HALF) {
        __half* C = (__half*)Cb;
#pragma unroll
        for (int mt = 0; mt < 4; mt++) {
#pragma unroll
            for (int nt = 0; nt < 8; nt++) {
                int row = bm + wm * 64 + mt * 16 + (lane >> 2);
                int col = bn + wn * 64 + nt * 8 + ((lane & 3) << 1);
                __half2 h0 = __float22half2_rn(make_float2(acc[mt][nt][0], acc[mt][nt][1]));
                __half2 h1 = __float22half2_rn(make_float2(acc[mt][nt][2], acc[mt][nt][3]));
                *reinterpret_cast<__half2*>(C + (long long)row * ldc + col) = h0;
                *reinterpret_cast<__half2*>(C + (long long)(row + 8) * ldc + col) = h1;
            }
        }
    } else if (OM == OM_F32A) {
        float* C = (float*)Cb;
#pragma unroll
        for (int mt = 0; mt < 4; mt++) {
#pragma unroll
            for (int nt = 0; nt < 8; nt++) {
                int row = bm + wm * 64 + mt * 16 + (lane >> 2);
                int col = bn + wn * 64 + nt * 8 + ((lane & 3) << 1);
                if (col < N) {
                    if (row < M) {
                        long long i0 = (long long)row * ldc + col;
                        float2 v;
                        v.x = alpha * acc[mt][nt][0];
                        v.y = alpha * acc[mt][nt][1];
                        *reinterpret_cast<float2*>(C + i0) = v;
                    }
                    if (row + 8 < M) {
                        long long i1 = (long long)(row + 8) * ldc + col;
                        float2 v;
                        v.x = alpha * acc[mt][nt][2];
                        v.y = alpha * acc[mt][nt][3];
                        *reinterpret_cast<float2*>(C + i1) = v;
                    }
                }
            }
        }
    } else if (OM == OM_HRES) {
        // add fp32 residual D, store fp16
        __half* C = (__half*)Cb;
#pragma unroll
        for (int mt = 0; mt < 4; mt++) {
#pragma unroll
            for (int nt = 0; nt < 8; nt++) {
                int row = bm + wm * 64 + mt * 16 + (lane >> 2);
                int col = bn + wn * 64 + nt * 8 + ((lane & 3) << 1);
                if (col < N) {
                    if (row < M) {
                        long long i0 = (long long)row * ldc + col;
                        float2 d0 = *reinterpret_cast<const float2*>(D + i0);
                        __half2 h = __float22half2_rn(
                            make_float2(acc[mt][nt][0] + d0.x, acc[mt][nt][1] + d0.y));
                        *reinterpret_cast<__half2*>(C + i0) = h;
                    }
                    if (row + 8 < M) {
                        long long i1 = (long long)(row + 8) * ldc + col;
                        float2 d1 = *reinterpret_cast<const float2*>(D + i1);
                        __half2 h = __float22half2_rn(
                            make_float2(acc[mt][nt][2] + d1.x, acc[mt][nt][3] + d1.y));
                        *reinterpret_cast<__half2*>(C + i1) = h;
                    }
                }
            }
        }
    } else {   // OM_TRANS: scatter C[b][n][m%FEAT] as fp16 via smem staging
        float* Cs = reinterpret_cast<float*>(smem);
        __half* Ch = (__half*)Cb;
        __syncthreads();
#pragma unroll
        for (int mt = 0; mt < 4; mt++) {
#pragma unroll
            for (int nt = 0; nt < 8; nt++) {
                int nl = wn * 64 + nt * 8 + ((lane & 3) << 1);
                int m0 = wm * 64 + mt * 16 + (lane >> 2);
                Cs[nl * 132 + m0]           = acc[mt][nt][0];
                Cs[(nl + 1) * 132 + m0]     = acc[mt][nt][1];
                Cs[nl * 132 + m0 + 8]       = acc[mt][nt][2];
                Cs[(nl + 1) * 132 + m0 + 8] = acc[mt][nt][3];
            }
        }
        __syncthreads();
#pragma unroll
        for (int it = 0; it < 32; it++) {
            int linear = tid + it * 128;
            int row = linear >> 5;
            int c4  = linear & 31;
            int n_g = bn + row;
            int m_g = bm + c4 * 4;
            int bb  = m_g / FEAT;
            int mm  = m_g - bb * FEAT;
            float4 v = *reinterpret_cast<const float4*>(&Cs[row * 132 + c4 * 4]);
            __half2 h0 = __float22half2_rn(make_float2(v.x, v.y));
            __half2 h1 = __float22half2_rn(make_float2(v.z, v.w));
            __half2* dst = reinterpret_cast<__half2*>(
                Ch + (long long)bb * sCb + (long long)n_g * ldc + mm);
            dst[0] = h0; dst[1] = h1;
        }
    }
}

// ---------------- fused persistent QKV (R8 exact) ----------------
#define QKV_TILES_PER_OP 1280
#define QKV_NTILES 3840

__global__ __launch_bounds__(128, 2)
void qkv_kernel(const __half* __restrict__ qryh, const __half* __restrict__ suph,
                const __half* __restrict__ wq, const __half* __restrict__ wk,
                const __half* __restrict__ wv,
                __half* __restrict__ qT, __half* __restrict__ kT, __half* __restrict__ vN)
{
    extern __shared__ char smem[];
    const uint32_t sb = smem_u32(smem);
    const long long sX = (long long)FEAT * NPTS;

    for (int t = blockIdx.x; t < QKV_NTILES; t += gridDim.x) {
        int op = t / QKV_TILES_PER_OP;
        int r  = t - op * QKV_TILES_PER_OP;
        int bm = (r >> 4) * 128;
        int bn = (r & 15) * 128;
        __syncthreads();
        if (op == 0) {
            run_tile_h<OM_HALF>(suph, wq, (char*)qT, nullptr,
                                NB * FEAT, 2048, 2048, 2048, 2048, 2048, 0,
                                bm, bn, 1.f, sb, smem);
        } else if (op == 1) {
            run_tile_h<OM_HALF>(qryh, wk, (char*)kT, nullptr,
                                NB * FEAT, 2048, 2048, 2048, 2048, 2048, 0,
                                bm, bn, 1.f, sb, smem);
        } else {
            run_tile_h<OM_TRANS>(qryh, wv, (char*)vN, nullptr,
                                 NB * FEAT, 2048, 2048, 2048, 2048, 320, sX,
                                 bm, bn, 1.f, sb, smem);
        }
    }
}

// ---------------- generic persistent batched GEMM ----------------
template<int OM>
__global__ __launch_bounds__(128, 2)
void gemm_h_kernel(const __half* __restrict__ Ag, const __half* __restrict__ Bg,
                   char* __restrict__ Cg, const float* __restrict__ Dg,
                   int M, int N, int K, int lda, int ldb, int ldc,
                   long long sA, long long sB, long long sC, long long sD,
                   float alpha, int ntiles, int tn)
{
    extern __shared__ char smem[];
    const uint32_t sb = smem_u32(smem);
    const int per = ((M + 127) >> 7) * tn;
    const int esz = (OM == OM_HALF || OM == OM_TRANS || OM == OM_HRES) ? 2 : 4;

    for (int t = blockIdx.x; t < ntiles; t += gridDim.x) {
        int b = t / per;
        int r = t - b * per;
        int bm = (r / tn) * 128;
        int bn = (r % tn) * 128;
        __syncthreads();
        run_tile_h<OM>(Ag + (long long)b * sA, Bg + (long long)b * sB,
                       Cg + (long long)b * sC * esz,
                       Dg ? (Dg + (long long)b * sD) : nullptr,
                       M, N, K, lda, ldb, ldc, 0, bm, bn, alpha, sb, smem);
    }
}

// ---------------- fused convert (R13 exact): 1 launch, STG.128, MLP=2 ----------------
#define CP_B0 2621440LL   // support pairs
#define CP_B1 5242880LL   // + query
#define CP_B2 5767168LL   // + Wq
#define CP_B3 6291456LL   // + Wk
#define CP_B4 6815744LL   // + Wv

__device__ __forceinline__ uint32_t pack_h2(float x, float y) {
    __half2 h = __float22half2_rn(make_float2(x, y));
    return *reinterpret_cast<uint32_t*>(&h);
}

__global__ __launch_bounds__(256) void cvt_all_kernel(
    const float* __restrict__ s,  const float* __restrict__ q,
    const float* __restrict__ w0, const float* __restrict__ w1, const float* __restrict__ w2,
    __half* __restrict__ sh, __half* __restrict__ qh,
    __half* __restrict__ h0, __half* __restrict__ h1, __half* __restrict__ h2)
{
    long long blk = (long long)blockIdx.x * 256;
    const float* src; __half* dst; long long off;
    if (blk < CP_B0)      { src = s;  dst = sh; off = blk; }
    else if (blk < CP_B1) { src = q;  dst = qh; off = blk - CP_B0; }
    else if (blk < CP_B2) { src = w0; dst = h0; off = blk - CP_B1; }
    else if (blk < CP_B3) { src = w1; dst = h1; off = blk - CP_B2; }
    else                  { src = w2; dst = h2; off = blk - CP_B3; }
    off += threadIdx.x;
    const float4* s4 = reinterpret_cast<const float4*>(src);
    float4 a = s4[2 * off];
    float4 b = s4[2 * off + 1];
    uint4 u;
    u.x = pack_h2(a.x, a.y);
    u.y = pack_h2(a.z, a.w);
    u.z = pack_h2(b.x, b.y);
    u.w = pack_h2(b.z, b.w);
    reinterpret_cast<uint4*>(dst)[off] = u;
}

// ---------------- warp-per-row softmax (R10, measured 7.7us) ----------------
__global__ __launch_bounds__(256) void softmax_kernel(const float* __restrict__ attn,
                                                      __half* __restrict__ probs)
{
    const int lane = threadIdx.x & 31;
    const int wrow = (blockIdx.x << 3) + (threadIdx.x >> 5);
    const float* row = attn + (long long)wrow * FEAT;

    float v[10];
    float m = -1e30f;
#pragma unroll
    for (int j = 0; j < 10; j++) {
        v[j] = row[lane + 32 * j];
        m = fmaxf(m, v[j]);
    }
#pragma unroll
    for (int s = 16; s > 0; s >>= 1)
        m = fmaxf(m, __shfl_xor_sync(0xffffffff, m, s));
    float sum = 0.f;
#pragma unroll
    for (int j = 0; j < 10; j++) {
        v[j] = expf(v[j] - m);
        sum += v[j];
    }
#pragma unroll
    for (int s = 16; s > 0; s >>= 1)
        sum += __shfl_xor_sync(0xffffffff, sum, s);
    float inv = 1.f / sum;
    __half* orow = probs + (long long)wrow * FEAT;
#pragma unroll
    for (int j = 0; j < 10; j++)
        orow[lane + 32 * j] = __float2half(v[j] * inv);
}

// ---------------- LayerNorm over fp16 tmp ----------------
__global__ __launch_bounds__(256) void ln_kernel(const __half* __restrict__ tp,
                                                 const float* __restrict__ gamma,
                                                 const float* __restrict__ beta,
                                                 float* __restrict__ out)
{
    const int b = blockIdx.y;
    const int o = blockIdx.x * 256 + threadIdx.x;
    const __half* base = tp + (long long)b * (FEAT * NPTS) + o;
    float s = 0.f, s2 = 0.f;
#pragma unroll 4
    for (int l = 0; l < FEAT; l++) {
        float v = __half2float(base[(long long)l * NPTS]);
        s += v;
        s2 += v * v;
    }
    const float inv = 1.f / FEAT;
    float mu = s * inv;
    float var = s2 * inv - mu * mu;
    float rstd = rsqrtf(var + 1e-5f);
    float* ob = out + (long long)b * (FEAT * NPTS) + o;
#pragma unroll 4
    for (int l = 0; l < FEAT; l++) {
        float v = __half2float(base[(long long)l * NPTS]);
        ob[(long long)l * NPTS] = (v - mu) * rstd * gamma[l] + beta[l];
    }
}

// ---------------- launch ----------------
extern "C" void kernel_launch(void* const* d_in, const int* in_sizes, int n_in,
                              void* d_out, int out_size)
{
    const float* query   = (const float*)d_in[0];
    const float* support = (const float*)d_in[1];
    const float* Wq      = (const float*)d_in[2];
    const float* Wk      = (const float*)d_in[3];
    const float* Wv      = (const float*)d_in[4];
    const float* gamma   = (const float*)d_in[5];
    const float* beta    = (const float*)d_in[6];
    float* out = (float*)d_out;

    void* sp = nullptr;
    cudaGetSymbolAddress(&sp, g_scratch);
    char* S = (char*)sp;
    __half* suph = (__half*)(S + O_SUPH);
    __half* qryh = (__half*)(S + O_QRYH);
    __half* wqh  = (__half*)(S + O_WQH);
    __half* wkh  = (__half*)(S + O_WKH);
    __half* wvh  = (__half*)(S + O_WVH);
    __half* qT   = (__half*)(S + O_QTH);
    __half* kT   = (__half*)(S + O_KTH);
    __half* vN   = (__half*)(S + O_VNH);
    float*  atf  = (float*)(S + O_ATF);
    __half* prh  = (__half*)(S + O_PRH);
    __half* tph  = (__half*)(S + O_TMPH);

    const long long sXh = (long long)FEAT * NPTS;     // 655360 (halfs)
    const long long sAt = (long long)FEAT * FEAT;     // 102400

    static bool attr_set = false;
    if (!attr_set) {
        cudaFuncSetAttribute(qkv_kernel,
                             cudaFuncAttributeMaxDynamicSharedMemorySize, SMEM_TOTAL_BYTES);
        cudaFuncSetAttribute(gemm_h_kernel<OM_F32A>,
                             cudaFuncAttributeMaxDynamicSharedMemorySize, SMEM_TOTAL_BYTES);
        cudaFuncSetAttribute(gemm_h_kernel<OM_HRES>,
                             cudaFuncAttributeMaxDynamicSharedMemorySize, SMEM_TOTAL_BYTES);
        attr_set = true;
    }

    const size_t smb = SMEM_TOTAL_BYTES;
    const float alpha = 1.0f / sqrtf((float)FEAT);

    // single fused fp32->fp16 convert (support, query, Wq, Wk, Wv)
    cvt_all_kernel<<<(int)(CP_B4 / 256), 256>>>(
        support, query, Wq, Wk, Wv, suph, qryh, wqh, wkh, wvh);

    // fused persistent QKV (R8 exact: 128x128 tiles, 2 CTAs/SM)
    qkv_kernel<<<296, 128, smb>>>(qryh, suph, wqh, wkh, wvh, qT, kT, vN);
    // attn logits fp32: M=N=320, K=2048
    gemm_h_kernel<OM_F32A><<<288, 128, smb>>>(
        qT, kT, (char*)atf, nullptr, 320, 320, 2048, 2048, 2048, 320,
        sXh, sXh, sAt, 0, alpha, 288, 3);
    // warp-per-row softmax -> fp16 probs
    softmax_kernel<<<NB * FEAT / 8, 256>>>(atf, prh);
    // AV + residual -> fp16 tmp: M=320, N=2048, K=320
    gemm_h_kernel<OM_HRES><<<296, 128, smb>>>(
        prh, vN, (char*)tph, query, 320, 2048, 320, 320, 320, 2048,
        sAt, sXh, sXh, sXh, 1.f, 1536, 16);
    // LayerNorm over fp16 tmp
    ln_kernel<<<dim3(NPTS / 256, NB), 256>>>(tph, gamma, beta, out);
}

// round 17
// speedup vs baseline: 1.1607x; 1.0446x over previous
#include <cuda_runtime.h>
#include <cuda_fp16.h>
#include <cstdint>
#include <cmath>

#define NB 32
#define FEAT 320
#define NPTS 2048

static __device__ float g_scratch[87162880];   // 348 MB

// byte offsets into scratch
#define O_SUPH 0LL
#define O_QRYH 41943040LL
#define O_WQH  83886080LL
#define O_WKH  92274688LL
#define O_WVH  100663296LL
#define O_QTH  109051904LL
#define O_KTH  150994944LL
#define O_VNH  192937984LL
#define O_ATF  234881024LL
#define O_PRH  247988224LL
#define O_TMPH 254541824LL

#define STAGE_BYTES 32768          // A 16KB + B 16KB (fp16, BK=64)
#define SMEM_TOTAL_BYTES (3 * STAGE_BYTES)

#define OM_HALF   0
#define OM_TRANS  1
#define OM_F32A   2
#define OM_HRES   3   // +fp16 residual D, store fp16

// ---------------- PTX helpers ----------------
__device__ __forceinline__ uint32_t smem_u32(const void* p) {
    uint32_t a;
    asm("{ .reg .u64 t; cvta.to.shared.u64 t, %1; cvt.u32.u64 %0, t; }" : "=r"(a) : "l"(p));
    return a;
}

__device__ __forceinline__ void mma_f16(float* d, const uint32_t* a, const uint32_t* b) {
    asm volatile(
        "mma.sync.aligned.m16n8k16.row.col.f32.f16.f16.f32 "
        "{%0,%1,%2,%3}, {%4,%5,%6,%7}, {%8,%9}, {%0,%1,%2,%3};"
        : "+f"(d[0]), "+f"(d[1]), "+f"(d[2]), "+f"(d[3])
        : "r"(a[0]), "r"(a[1]), "r"(a[2]), "r"(a[3]), "r"(b[0]), "r"(b[1]));
}

__device__ __forceinline__ void ldsm4(uint32_t* r, uint32_t addr) {
    asm volatile("ldmatrix.sync.aligned.m8n8.x4.shared.b16 {%0,%1,%2,%3}, [%4];"
                 : "=r"(r[0]), "=r"(r[1]), "=r"(r[2]), "=r"(r[3]) : "r"(addr));
}

__device__ __forceinline__ void cpasync16(uint32_t dst, const void* src, bool pred) {
    int sz = pred ? 16 : 0;
    asm volatile("cp.async.cg.shared.global [%0], [%1], 16, %2;"
                 :: "r"(dst), "l"(src), "r"(sz) : "memory");
}
#define CP_COMMIT() asm volatile("cp.async.commit_group;" ::: "memory")
#define CP_WAIT1()  asm volatile("cp.async.wait_group 1;" ::: "memory")

// ---------------- fp16 tile core (register-pipelined) — R8-proven ----------------
template<int OM>
__device__ __forceinline__ void run_tile_h(
    const __half* __restrict__ A, const __half* __restrict__ B,
    char* __restrict__ Cb, const char* __restrict__ D,
    int M, int N, int K, int lda, int ldb, int ldc, long long sCb,
    int bm, int bn, float alpha, uint32_t sb, char* smem)
{
    const int tid  = threadIdx.x;
    const int lane = tid & 31;
    const int warp = tid >> 5;
    const int wm = warp & 1;
    const int wn = warp >> 1;

    const int r0  = tid >> 3;          // 0..15
    const int seg = tid & 7;
    const uint32_t xorterm = (uint32_t)((seg ^ (r0 & 7)) << 4);

    const int mrowA = ((lane >> 3) & 1) * 8 + (lane & 7);
    const int khA   = lane >> 4;              // 0/1
    const int nrowB = (lane >> 4) * 8 + (lane & 7);
    const int khB   = (lane >> 3) & 1;
    uint32_t offA[4], phA[4], offB[4], phB[4];
#pragma unroll
    for (int mt = 0; mt < 4; mt++) {
        int rowA = wm * 64 + mt * 16 + mrowA;
        offA[mt] = (uint32_t)(rowA * 128);
        phA[mt]  = (uint32_t)(rowA & 7);
    }
#pragma unroll
    for (int np = 0; np < 4; np++) {
        int rowB = wn * 64 + np * 16 + nrowB;
        offB[np] = (uint32_t)(rowB * 128);
        phB[np]  = (uint32_t)(rowB & 7);
    }

    float acc[4][8][4];
#pragma unroll
    for (int i = 0; i < 4; i++)
#pragma unroll
        for (int j = 0; j < 8; j++)
#pragma unroll
            for (int r = 0; r < 4; r++) acc[i][j][r] = 0.f;

    const int NC = K >> 6;   // BK=64

    auto ISSUE = [&](int c) {
        const int k0 = c << 6;
        const uint32_t aB = sb + (uint32_t)((c % 3) * STAGE_BYTES);
        const uint32_t bB = aB + 16384;
#pragma unroll
        for (int i = 0; i < 8; i++) {
            int r = r0 + 16 * i;
            int gr = bm + r;
            bool p = gr < M;
            cpasync16(aB + (uint32_t)(r * 128) + xorterm,
                      A + (long long)(p ? gr : 0) * lda + k0 + seg * 8, p);
        }
#pragma unroll
        for (int i = 0; i < 8; i++) {
            int r = r0 + 16 * i;
            int gn = bn + r;
            bool p = gn < N;
            cpasync16(bB + (uint32_t)(r * 128) + xorterm,
                      B + (long long)(p ? gn : 0) * ldb + k0 + seg * 8, p);
        }
        CP_COMMIT();
    };

    uint32_t afr[2][4][4];
    uint32_t bfr[2][8][2];

    ISSUE(0);
    ISSUE(1);

    for (int c = 0; c < NC; c++) {
        CP_WAIT1();
        __syncthreads();

        const uint32_t aB = sb + (uint32_t)((c % 3) * STAGE_BYTES);
        const uint32_t bB = aB + 16384;

        {
            const uint32_t s16 = (uint32_t)khA;
#pragma unroll
            for (int mt = 0; mt < 4; mt++)
                ldsm4(afr[0][mt], aB + offA[mt] + ((s16 ^ phA[mt]) << 4));
        }
        {
            const uint32_t s16 = (uint32_t)khB;
#pragma unroll
            for (int np = 0; np < 4; np++) {
                uint32_t r[4];
                ldsm4(r, bB + offB[np] + ((s16 ^ phB[np]) << 4));
                bfr[0][2 * np][0] = r[0];     bfr[0][2 * np][1] = r[1];
                bfr[0][2 * np + 1][0] = r[2]; bfr[0][2 * np + 1][1] = r[3];
            }
        }

        if (c + 2 < NC) ISSUE(c + 2);
        else CP_COMMIT();

#pragma unroll
        for (int ks = 0; ks < 4; ks++) {
            const int cur = ks & 1;
            const int nxt = cur ^ 1;
            if (ks < 3) {
                const uint32_t sA16 = (uint32_t)(2 * (ks + 1) + khA);
#pragma unroll
                for (int mt = 0; mt < 4; mt++)
                    ldsm4(afr[nxt][mt], aB + offA[mt] + ((sA16 ^ phA[mt]) << 4));
                const uint32_t sB16 = (uint32_t)(2 * (ks + 1) + khB);
#pragma unroll
                for (int np = 0; np < 4; np++) {
                    uint32_t r[4];
                    ldsm4(r, bB + offB[np] + ((sB16 ^ phB[np]) << 4));
                    bfr[nxt][2 * np][0] = r[0];     bfr[nxt][2 * np][1] = r[1];
                    bfr[nxt][2 * np + 1][0] = r[2]; bfr[nxt][2 * np + 1][1] = r[3];
                }
            }
#pragma unroll
            for (int mt = 0; mt < 4; mt++)
#pragma unroll
                for (int nt = 0; nt < 8; nt++)
                    mma_f16(acc[mt][nt], afr[cur][mt], bfr[cur][nt]);
        }
    }

    // ---------------- epilogues ----------------
    if (OM == OM_HALF) {
        __half* C = (__half*)Cb;
#pragma unroll
        for (int mt = 0; mt < 4; mt++) {
#pragma unroll
            for (int nt = 0; nt < 8; nt++) {
                int row = bm + wm * 64 + mt * 16 + (lane >> 2);
                int col = bn + wn * 64 + nt * 8 + ((lane & 3) << 1);
                __half2 h0 = __float22half2_rn(make_float2(acc[mt][nt][0], acc[mt][nt][1]));
                __half2 h1 = __float22half2_rn(make_float2(acc[mt][nt][2], acc[mt][nt][3]));
                *reinterpret_cast<__half2*>(C + (long long)row * ldc + col) = h0;
                *reinterpret_cast<__half2*>(C + (long long)(row + 8) * ldc + col) = h1;
            }
        }
    } else if (OM == OM_F32A) {
        float* C = (float*)Cb;
#pragma unroll
        for (int mt = 0; mt < 4; mt++) {
#pragma unroll
            for (int nt = 0; nt < 8; nt++) {
                int row = bm + wm * 64 + mt * 16 + (lane >> 2);
                int col = bn + wn * 64 + nt * 8 + ((lane & 3) << 1);
                if (col < N) {
                    if (row < M) {
                        long long i0 = (long long)row * ldc + col;
                        float2 v;
                        v.x = alpha * acc[mt][nt][0];
                        v.y = alpha * acc[mt][nt][1];
                        *reinterpret_cast<float2*>(C + i0) = v;
                    }
                    if (row + 8 < M) {
                        long long i1 = (long long)(row + 8) * ldc + col;
                        float2 v;
                        v.x = alpha * acc[mt][nt][2];
                        v.y = alpha * acc[mt][nt][3];
                        *reinterpret_cast<float2*>(C + i1) = v;
                    }
                }
            }
        }
    } else if (OM == OM_HRES) {
        // add fp16 residual D, store fp16
        __half* C = (__half*)Cb;
        const __half* Dh = (const __half*)D;
#pragma unroll
        for (int mt = 0; mt < 4; mt++) {
#pragma unroll
            for (int nt = 0; nt < 8; nt++) {
                int row = bm + wm * 64 + mt * 16 + (lane >> 2);
                int col = bn + wn * 64 + nt * 8 + ((lane & 3) << 1);
                if (col < N) {
                    if (row < M) {
                        long long i0 = (long long)row * ldc + col;
                        float2 d0 = __half22float2(*reinterpret_cast<const __half2*>(Dh + i0));
                        __half2 h = __float22half2_rn(
                            make_float2(acc[mt][nt][0] + d0.x, acc[mt][nt][1] + d0.y));
                        *reinterpret_cast<__half2*>(C + i0) = h;
                    }
                    if (row + 8 < M) {
                        long long i1 = (long long)(row + 8) * ldc + col;
                        float2 d1 = __half22float2(*reinterpret_cast<const __half2*>(Dh + i1));
                        __half2 h = __float22half2_rn(
                            make_float2(acc[mt][nt][2] + d1.x, acc[mt][nt][3] + d1.y));
                        *reinterpret_cast<__half2*>(C + i1) = h;
                    }
                }
            }
        }
    } else {   // OM_TRANS: scatter C[b][n][m%FEAT] as fp16 via smem staging
        float* Cs = reinterpret_cast<float*>(smem);
        __half* Ch = (__half*)Cb;
        __syncthreads();
#pragma unroll
        for (int mt = 0; mt < 4; mt++) {
#pragma unroll
            for (int nt = 0; nt < 8; nt++) {
                int nl = wn * 64 + nt * 8 + ((lane & 3) << 1);
                int m0 = wm * 64 + mt * 16 + (lane >> 2);
                Cs[nl * 132 + m0]           = acc[mt][nt][0];
                Cs[(nl + 1) * 132 + m0]     = acc[mt][nt][1];
                Cs[nl * 132 + m0 + 8]       = acc[mt][nt][2];
                Cs[(nl + 1) * 132 + m0 + 8] = acc[mt][nt][3];
            }
        }
        __syncthreads();
#pragma unroll
        for (int it = 0; it < 32; it++) {
            int linear = tid + it * 128;
            int row = linear >> 5;
            int c4  = linear & 31;
            int n_g = bn + row;
            int m_g = bm + c4 * 4;
            int bb  = m_g / FEAT;
            int mm  = m_g - bb * FEAT;
            float4 v = *reinterpret_cast<const float4*>(&Cs[row * 132 + c4 * 4]);
            __half2 h0 = __float22half2_rn(make_float2(v.x, v.y));
            __half2 h1 = __float22half2_rn(make_float2(v.z, v.w));
            __half2* dst = reinterpret_cast<__half2*>(
                Ch + (long long)bb * sCb + (long long)n_g * ldc + mm);
            dst[0] = h0; dst[1] = h1;
        }
    }
}

// ---------------- fused persistent QKV (R8 exact) ----------------
#define QKV_TILES_PER_OP 1280
#define QKV_NTILES 3840

__global__ __launch_bounds__(128, 2)
void qkv_kernel(const __half* __restrict__ qryh, const __half* __restrict__ suph,
                const __half* __restrict__ wq, const __half* __restrict__ wk,
                const __half* __restrict__ wv,
                __half* __restrict__ qT, __half* __restrict__ kT, __half* __restrict__ vN)
{
    extern __shared__ char smem[];
    const uint32_t sb = smem_u32(smem);
    const long long sX = (long long)FEAT * NPTS;

    for (int t = blockIdx.x; t < QKV_NTILES; t += gridDim.x) {
        int op = t / QKV_TILES_PER_OP;
        int r  = t - op * QKV_TILES_PER_OP;
        int bm = (r >> 4) * 128;
        int bn = (r & 15) * 128;
        __syncthreads();
        if (op == 0) {
            run_tile_h<OM_HALF>(suph, wq, (char*)qT, nullptr,
                                NB * FEAT, 2048, 2048, 2048, 2048, 2048, 0,
                                bm, bn, 1.f, sb, smem);
        } else if (op == 1) {
            run_tile_h<OM_HALF>(qryh, wk, (char*)kT, nullptr,
                                NB * FEAT, 2048, 2048, 2048, 2048, 2048, 0,
                                bm, bn, 1.f, sb, smem);
        } else {
            run_tile_h<OM_TRANS>(qryh, wv, (char*)vN, nullptr,
                                 NB * FEAT, 2048, 2048, 2048, 2048, 320, sX,
                                 bm, bn, 1.f, sb, smem);
        }
    }
}

// ---------------- generic persistent batched GEMM ----------------
template<int OM>
__global__ __launch_bounds__(128, 2)
void gemm_h_kernel(const __half* __restrict__ Ag, const __half* __restrict__ Bg,
                   char* __restrict__ Cg, const char* __restrict__ Dg,
                   int M, int N, int K, int lda, int ldb, int ldc,
                   long long sA, long long sB, long long sC, long long sD,
                   float alpha, int ntiles, int tn)
{
    extern __shared__ char smem[];
    const uint32_t sb = smem_u32(smem);
    const int per = ((M + 127) >> 7) * tn;
    const int esz = (OM == OM_HALF || OM == OM_TRANS || OM == OM_HRES) ? 2 : 4;
    const int dsz = (OM == OM_HRES) ? 2 : 4;

    for (int t = blockIdx.x; t < ntiles; t += gridDim.x) {
        int b = t / per;
        int r = t - b * per;
        int bm = (r / tn) * 128;
        int bn = (r % tn) * 128;
        __syncthreads();
        run_tile_h<OM>(Ag + (long long)b * sA, Bg + (long long)b * sB,
                       Cg + (long long)b * sC * esz,
                       Dg ? (Dg + (long long)b * sD * dsz) : nullptr,
                       M, N, K, lda, ldb, ldc, 0, bm, bn, alpha, sb, smem);
    }
}

// ---------------- fused convert: 1 launch, STG.128, 4 pairs/thread (MLP=8) ----------------
// Pair = 2 adjacent float4 in -> 1 uint4 out. Block owns 1024 pairs; thread
// processes pairs (tid + i*256), i=0..3 — lane-contiguous per iteration.
// All region boundaries are multiples of 1024 pairs.
#define CP_B0 2621440LL   // support pairs
#define CP_B1 5242880LL   // + query
#define CP_B2 5767168LL   // + Wq
#define CP_B3 6291456LL   // + Wk
#define CP_B4 6815744LL   // + Wv

__device__ __forceinline__ uint32_t pack_h2(float x, float y) {
    __half2 h = __float22half2_rn(make_float2(x, y));
    return *reinterpret_cast<uint32_t*>(&h);
}

__global__ __launch_bounds__(256) void cvt_all_kernel(
    const float* __restrict__ s,  const float* __restrict__ q,
    const float* __restrict__ w0, const float* __restrict__ w1, const float* __restrict__ w2,
    __half* __restrict__ sh, __half* __restrict__ qh,
    __half* __restrict__ h0, __half* __restrict__ h1, __half* __restrict__ h2)
{
    long long blk = (long long)blockIdx.x * 1024;
    const float* src; __half* dst; long long off0;
    if (blk < CP_B0)      { src = s;  dst = sh; off0 = blk; }
    else if (blk < CP_B1) { src = q;  dst = qh; off0 = blk - CP_B0; }
    else if (blk < CP_B2) { src = w0; dst = h0; off0 = blk - CP_B1; }
    else if (blk < CP_B3) { src = w1; dst = h1; off0 = blk - CP_B2; }
    else                  { src = w2; dst = h2; off0 = blk - CP_B3; }
    off0 += threadIdx.x;
    const float4* s4 = reinterpret_cast<const float4*>(src);
    float4 a[4], b[4];
#pragma unroll
    for (int i = 0; i < 4; i++) {
        long long off = off0 + i * 256;
        a[i] = s4[2 * off];
        b[i] = s4[2 * off + 1];
    }
#pragma unroll
    for (int i = 0; i < 4; i++) {
        long long off = off0 + i * 256;
        uint4 u;
        u.x = pack_h2(a[i].x, a[i].y);
        u.y = pack_h2(a[i].z, a[i].w);
        u.z = pack_h2(b[i].x, b[i].y);
        u.w = pack_h2(b[i].z, b[i].w);
        reinterpret_cast<uint4*>(dst)[off] = u;
    }
}

// ---------------- warp-per-row softmax (R10, measured 7.7us) ----------------
__global__ __launch_bounds__(256) void softmax_kernel(const float* __restrict__ attn,
                                                      __half* __restrict__ probs)
{
    const int lane = threadIdx.x & 31;
    const int wrow = (blockIdx.x << 3) + (threadIdx.x >> 5);
    const float* row = attn + (long long)wrow * FEAT;

    float v[10];
    float m = -1e30f;
#pragma unroll
    for (int j = 0; j < 10; j++) {
        v[j] = row[lane + 32 * j];
        m = fmaxf(m, v[j]);
    }
#pragma unroll
    for (int s = 16; s > 0; s >>= 1)
        m = fmaxf(m, __shfl_xor_sync(0xffffffff, m, s));
    float sum = 0.f;
#pragma unroll
    for (int j = 0; j < 10; j++) {
        v[j] = expf(v[j] - m);
        sum += v[j];
    }
#pragma unroll
    for (int s = 16; s > 0; s >>= 1)
        sum += __shfl_xor_sync(0xffffffff, sum, s);
    float inv = 1.f / sum;
    __half* orow = probs + (long long)wrow * FEAT;
#pragma unroll
    for (int j = 0; j < 10; j++)
        orow[lane + 32 * j] = __float2half(v[j] * inv);
}

// ---------------- LayerNorm over fp16 tmp ----------------
__global__ __launch_bounds__(256) void ln_kernel(const __half* __restrict__ tp,
                                                 const float* __restrict__ gamma,
                                                 const float* __restrict__ beta,
                                                 float* __restrict__ out)
{
    const int b = blockIdx.y;
    const int o = blockIdx.x * 256 + threadIdx.x;
    const __half* base = tp + (long long)b * (FEAT * NPTS) + o;
    float s = 0.f, s2 = 0.f;
#pragma unroll 4
    for (int l = 0; l < FEAT; l++) {
        float v = __half2float(base[(long long)l * NPTS]);
        s += v;
        s2 += v * v;
    }
    const float inv = 1.f / FEAT;
    float mu = s * inv;
    float var = s2 * inv - mu * mu;
    float rstd = rsqrtf(var + 1e-5f);
    float* ob = out + (long long)b * (FEAT * NPTS) + o;
#pragma unroll 4
    for (int l = 0; l < FEAT; l++) {
        float v = __half2float(base[(long long)l * NPTS]);
        ob[(long long)l * NPTS] = (v - mu) * rstd * gamma[l] + beta[l];
    }
}

// ---------------- launch ----------------
extern "C" void kernel_launch(void* const* d_in, const int* in_sizes, int n_in,
                              void* d_out, int out_size)
{
    const float* query   = (const float*)d_in[0];
    const float* support = (const float*)d_in[1];
    const float* Wq      = (const float*)d_in[2];
    const float* Wk      = (const float*)d_in[3];
    const float* Wv      = (const float*)d_in[4];
    const float* gamma   = (const float*)d_in[5];
    const float* beta    = (const float*)d_in[6];
    float* out = (float*)d_out;

    void* sp = nullptr;
    cudaGetSymbolAddress(&sp, g_scratch);
    char* S = (char*)sp;
    __half* suph = (__half*)(S + O_SUPH);
    __half* qryh = (__half*)(S + O_QRYH);
    __half* wqh  = (__half*)(S + O_WQH);
    __half* wkh  = (__half*)(S + O_WKH);
    __half* wvh  = (__half*)(S + O_WVH);
    __half* qT   = (__half*)(S + O_QTH);
    __half* kT   = (__half*)(S + O_KTH);
    __half* vN   = (__half*)(S + O_VNH);
    float*  atf  = (float*)(S + O_ATF);
    __half* prh  = (__half*)(S + O_PRH);
    __half* tph  = (__half*)(S + O_TMPH);

    const long long sXh = (long long)FEAT * NPTS;     // 655360 (halfs)
    const long long sAt = (long long)FEAT * FEAT;     // 102400

    static bool attr_set = false;
    if (!attr_set) {
        cudaFuncSetAttribute(qkv_kernel,
                             cudaFuncAttributeMaxDynamicSharedMemorySize, SMEM_TOTAL_BYTES);
        cudaFuncSetAttribute(gemm_h_kernel<OM_F32A>,
                             cudaFuncAttributeMaxDynamicSharedMemorySize, SMEM_TOTAL_BYTES);
        cudaFuncSetAttribute(gemm_h_kernel<OM_HRES>,
                             cudaFuncAttributeMaxDynamicSharedMemorySize, SMEM_TOTAL_BYTES);
        attr_set = true;
    }

    const size_t smb = SMEM_TOTAL_BYTES;
    const float alpha = 1.0f / sqrtf((float)FEAT);

    // single fused fp32->fp16 convert (support, query, Wq, Wk, Wv)
    cvt_all_kernel<<<(int)(CP_B4 / 1024), 256>>>(
        support, query, Wq, Wk, Wv, suph, qryh, wqh, wkh, wvh);

    // fused persistent QKV (R8 exact: 128x128 tiles, 2 CTAs/SM)
    qkv_kernel<<<296, 128, smb>>>(qryh, suph, wqh, wkh, wvh, qT, kT, vN);
    // attn logits fp32: M=N=320, K=2048
    gemm_h_kernel<OM_F32A><<<288, 128, smb>>>(
        qT, kT, (char*)atf, nullptr, 320, 320, 2048, 2048, 2048, 320,
        sXh, sXh, sAt, 0, alpha, 288, 3);
    // warp-per-row softmax -> fp16 probs
    softmax_kernel<<<NB * FEAT / 8, 256>>>(atf, prh);
    // AV + fp16 residual (qryh) -> fp16 tmp: M=320, N=2048, K=320
    gemm_h_kernel<OM_HRES><<<296, 128, smb>>>(
        prh, vN, (char*)tph, (const char*)qryh, 320, 2048, 320, 320, 320, 2048,
        sAt, sXh, sXh, sXh, 1.f, 1536, 16);
    // LayerNorm over fp16 tmp
    ln_kernel<<<dim3(NPTS / 256, NB), 256>>>(tph, gamma, beta, out);
}